// round 2
// baseline (speedup 1.0000x reference)
#include <cuda_runtime.h>
#include <math.h>

#define NN 1024
#define FF 128
#define H0C 192
#define H1C 96
#define BI 8
#define BJ 16
#define PPAIRS 128          // BI*BJ pairs per CTA
#define XPITCH 132          // Xs row pitch (floats), mult of 4
#define WPITCH 196          // W0 chunk pitch (floats)
#define W1PITCH 100         // W1 chunk pitch (floats)
#define HPITCH 128          // H0act pitch

// smem layout (floats):
//   Xs    [128][XPITCH]            = 16896
//   Wbuf  max(64*196, 64*100)=12544 (reused for W0 chunks, W1 chunks, reduction)
//   Hact  [192][128]               = 24576
#define SM_XS    0
#define SM_WBUF  (128 * XPITCH)
#define SM_HACT  (SM_WBUF + 12544)
#define SM_FLOATS (SM_HACT + H0C * HPITCH)
#define SMEM_BYTES (SM_FLOATS * 4)

__device__ __forceinline__ unsigned long long dup2(float w) {
    unsigned long long r;
    asm("mov.b64 %0, {%1, %1};" : "=l"(r) : "f"(w));
    return r;
}
__device__ __forceinline__ void ffma2(unsigned long long& acc,
                                      unsigned long long a, unsigned long long b) {
    asm("fma.rn.f32x2 %0, %1, %2, %0;" : "+l"(acc) : "l"(a), "l"(b));
}
__device__ __forceinline__ void unpack2(unsigned long long v, float& lo, float& hi) {
    asm("mov.b64 {%0, %1}, %2;" : "=f"(lo), "=f"(hi) : "l"(v));
}
__device__ __forceinline__ float leaky(float x) {
    return fmaxf(x, 0.0f) + 0.01f * fminf(x, 0.0f);
}

__global__ void __launch_bounds__(256, 1) edgenet_sim_kernel(
    const float* __restrict__ feat,
    const float* __restrict__ W0, const float* __restrict__ g0,
    const float* __restrict__ b0, const float* __restrict__ m0,
    const float* __restrict__ v0,
    const float* __restrict__ W1, const float* __restrict__ g1,
    const float* __restrict__ b1, const float* __restrict__ m1,
    const float* __restrict__ v1,
    const float* __restrict__ Wout, const float* __restrict__ bout,
    float* __restrict__ sim_out)
{
    extern __shared__ float sm[];
    float* Xs   = sm + SM_XS;
    float* Wbuf = sm + SM_WBUF;
    float* Hact = sm + SM_HACT;
    float* red  = sm + SM_WBUF;   // overlay after GEMM2

    const int tid = threadIdx.x;
    const int tg  = tid >> 4;     // 0..15 pair-group  (8 pairs each)
    const int tl  = tid & 15;     // 0..15 channel-group
    const int i0  = blockIdx.y * BI;
    const int j0  = blockIdx.x * BJ;

    // ---- Phase 0: Xs[f][p] = |feat[i][f] - feat[j][f]|,  p = pi*16 + pj ----
    {
        const int f  = tid & 127;
        const int dp = tid >> 7;               // {0,1}
        for (int p2 = 0; p2 < PPAIRS; p2 += 2) {
            int p = p2 + dp;
            int i = i0 + (p >> 4);
            int j = j0 + (p & 15);
            float a = feat[i * FF + f];
            float b = feat[j * FF + f];
            Xs[f * XPITCH + p] = fabsf(a - b);
        }
    }

    // ---- GEMM1: H0[c][p] = sum_f W0[c][f] * X[f][p], fused BN0 + leaky ----
    unsigned long long acc[12][4];
#pragma unroll
    for (int c = 0; c < 12; ++c)
#pragma unroll
        for (int q = 0; q < 4; ++q) acc[c][q] = 0ULL;

    for (int kc = 0; kc < 2; ++kc) {
        __syncthreads();
        // stage W0 chunk transposed: Wbuf[f_local][c], f_local in [0,64)
        for (int t = tid; t < 3072; t += 256) {
            int c  = t >> 4;
            int fq = t & 15;
            float4 w4 = *(const float4*)&W0[c * FF + kc * 64 + fq * 4];
            Wbuf[(fq * 4 + 0) * WPITCH + c] = w4.x;
            Wbuf[(fq * 4 + 1) * WPITCH + c] = w4.y;
            Wbuf[(fq * 4 + 2) * WPITCH + c] = w4.z;
            Wbuf[(fq * 4 + 3) * WPITCH + c] = w4.w;
        }
        __syncthreads();
#pragma unroll 2
        for (int f = 0; f < 64; ++f) {
            const float* xr = &Xs[((kc << 6) + f) * XPITCH + tg * 8];
            ulonglong2 xa = *(const ulonglong2*)(xr);
            ulonglong2 xb = *(const ulonglong2*)(xr + 4);
            unsigned long long xv[4] = {xa.x, xa.y, xb.x, xb.y};
            const float* wr = &Wbuf[f * WPITCH + tl * 12];
            float4 wA = *(const float4*)(wr);
            float4 wB = *(const float4*)(wr + 4);
            float4 wC = *(const float4*)(wr + 8);
            float wv[12] = {wA.x, wA.y, wA.z, wA.w, wB.x, wB.y, wB.z, wB.w,
                            wC.x, wC.y, wC.z, wC.w};
#pragma unroll
            for (int c = 0; c < 12; ++c) {
                unsigned long long wd = dup2(wv[c]);
#pragma unroll
                for (int q = 0; q < 4; ++q) ffma2(acc[c][q], wd, xv[q]);
            }
        }
    }

    // epilogue: BN0 + leaky -> Hact[c][p]
#pragma unroll
    for (int cc = 0; cc < 12; ++cc) {
        int c = tl * 12 + cc;
        float s = g0[c] * rsqrtf(v0[c] + 1e-5f);
        float t = b0[c] - m0[c] * s;
        float* hrow = &Hact[c * HPITCH + tg * 8];
#pragma unroll
        for (int q = 0; q < 4; ++q) {
            float lo, hi;
            unpack2(acc[cc][q], lo, hi);
            lo = leaky(lo * s + t);
            hi = leaky(hi * s + t);
            hrow[q * 2]     = lo;
            hrow[q * 2 + 1] = hi;
        }
    }

    // ---- GEMM2: H1[d][p] = sum_c W1[d][c] * Hact[c][p] ----
    unsigned long long acc2[6][4];
#pragma unroll
    for (int d = 0; d < 6; ++d)
#pragma unroll
        for (int q = 0; q < 4; ++q) acc2[d][q] = 0ULL;

    for (int kc = 0; kc < 3; ++kc) {
        __syncthreads();   // Wbuf reuse + (kc==0) Hact visibility
        // stage W1 chunk transposed: Wbuf[c_local][d]
        for (int t = tid; t < 1536; t += 256) {
            int d  = t >> 4;
            int cq = t & 15;
            float4 w4 = *(const float4*)&W1[d * H0C + kc * 64 + cq * 4];
            Wbuf[(cq * 4 + 0) * W1PITCH + d] = w4.x;
            Wbuf[(cq * 4 + 1) * W1PITCH + d] = w4.y;
            Wbuf[(cq * 4 + 2) * W1PITCH + d] = w4.z;
            Wbuf[(cq * 4 + 3) * W1PITCH + d] = w4.w;
        }
        __syncthreads();
#pragma unroll 2
        for (int c = 0; c < 64; ++c) {
            const float* xr = &Hact[((kc << 6) + c) * HPITCH + tg * 8];
            ulonglong2 xa = *(const ulonglong2*)(xr);
            ulonglong2 xb = *(const ulonglong2*)(xr + 4);
            unsigned long long xv[4] = {xa.x, xa.y, xb.x, xb.y};
            const float* wr = &Wbuf[c * W1PITCH + tl * 6];
            float2 wA = *(const float2*)(wr);
            float2 wB = *(const float2*)(wr + 2);
            float2 wC = *(const float2*)(wr + 4);
            float wv[6] = {wA.x, wA.y, wB.x, wB.y, wC.x, wC.y};
#pragma unroll
            for (int d = 0; d < 6; ++d) {
                unsigned long long wd = dup2(wv[d]);
#pragma unroll
                for (int q = 0; q < 4; ++q) ffma2(acc2[d][q], wd, xv[q]);
            }
        }
    }

    // epilogue: BN1 + leaky + fold Wout dot -> per-thread partial logits
    float part[8];
#pragma unroll
    for (int k = 0; k < 8; ++k) part[k] = 0.0f;
#pragma unroll
    for (int dd = 0; dd < 6; ++dd) {
        int d = tl * 6 + dd;
        float s  = g1[d] * rsqrtf(v1[d] + 1e-5f);
        float t  = b1[d] - m1[d] * s;
        float wo = Wout[d];
#pragma unroll
        for (int q = 0; q < 4; ++q) {
            float lo, hi;
            unpack2(acc2[dd][q], lo, hi);
            part[q * 2]     += wo * leaky(lo * s + t);
            part[q * 2 + 1] += wo * leaky(hi * s + t);
        }
    }

    __syncthreads();  // done reading Wbuf; overlay reduction buffer
#pragma unroll
    for (int k = 0; k < 8; ++k)
        red[tl * PPAIRS + tg * 8 + k] = part[k];
    __syncthreads();

    if (tid < PPAIRS) {
        int p = tid;
        float sum = 0.0f;
#pragma unroll
        for (int r = 0; r < 16; ++r) sum += red[r * PPAIRS + p];
        float logit = sum + bout[0];
        float simv  = 1.0f / (1.0f + expf(-logit));
        int i = i0 + (p >> 4);
        int j = j0 + (p & 15);
        sim_out[i * NN + j] = simv;
    }
}

// ---- pass 2: partial column sums of sim over 128-row slabs ----
__device__ float g_colpart[8][NN];

__global__ void colsum_kernel(const float* __restrict__ sim) {
    int j = blockIdx.x * 256 + threadIdx.x;   // gridDim.x = 4
    int slab = blockIdx.y;                    // 0..7
    float s = 0.0f;
    int ibase = slab * 128;
#pragma unroll 8
    for (int i = 0; i < 128; ++i) s += sim[(ibase + i) * NN + j];
    g_colpart[slab][j] = s;
}

// ---- pass 3: edge = (sim + eye + 1e-6) / colsum_over_i ----
__global__ void edge_kernel(const float* __restrict__ sim, float* __restrict__ edge) {
    int idx = blockIdx.x * 256 + threadIdx.x;
    int i = idx >> 10;
    int j = idx & (NN - 1);
    float denom = 1.0f + NN * 1e-6f;
#pragma unroll
    for (int r = 0; r < 8; ++r) denom += g_colpart[r][j];
    float v = sim[idx] + ((i == j) ? 1.0f : 0.0f) + 1e-6f;
    edge[idx] = v / denom;
}

extern "C" void kernel_launch(void* const* d_in, const int* in_sizes, int n_in,
                              void* d_out, int out_size) {
    const float* feat = (const float*)d_in[0];
    const float* W0   = (const float*)d_in[1];
    const float* g0   = (const float*)d_in[2];
    const float* b0   = (const float*)d_in[3];
    const float* m0   = (const float*)d_in[4];
    const float* v0   = (const float*)d_in[5];
    const float* W1   = (const float*)d_in[6];
    const float* g1   = (const float*)d_in[7];
    const float* b1   = (const float*)d_in[8];
    const float* m1   = (const float*)d_in[9];
    const float* v1   = (const float*)d_in[10];
    const float* Wout = (const float*)d_in[11];
    const float* bout = (const float*)d_in[12];

    float* out  = (float*)d_out;
    float* edge = out;              // edge_feat [1,N,N] first
    float* sim  = out + NN * NN;    // sim_val [N,N] second

    cudaFuncSetAttribute(edgenet_sim_kernel,
                         cudaFuncAttributeMaxDynamicSharedMemorySize, SMEM_BYTES);

    dim3 grid(NN / BJ, NN / BI);   // (64, 128)
    edgenet_sim_kernel<<<grid, 256, SMEM_BYTES>>>(
        feat, W0, g0, b0, m0, v0, W1, g1, b1, m1, v1, Wout, bout, sim);

    colsum_kernel<<<dim3(4, 8), 256>>>(sim);
    edge_kernel<<<(NN * NN) / 256, 256>>>(sim, edge);
}

// round 5
// speedup vs baseline: 2.5495x; 2.5495x over previous
#include <cuda_runtime.h>
#include <math.h>
#include <cstdint>

#define NN 1024
#define FF 128
#define H0C 192
#define H1C 96
#define THREADS 256
#define GRIDX 148
#define TILES 16384          // 1024 i  x  16 j-blocks of 64

// ---------------- SMEM layout (bytes) ----------------
// W0frag: [24 nt][16 kt][32] uint2  = 98304
// W1frag: [12 nt][24 kt][32] uint2  = 73728
// XH:     union( Xfrag [4 mt][16 kt][64] uint2 = 32768,
//                Hfrag [4 mt][24 kt][64] uint2 = 49152 ) = 49152
#define SM_W0F   0
#define SM_W1F   98304
#define SM_XH    172032
#define SM_BN0   221184      // 192 floats
#define SM_BN1   221952      // 96 floats
#define SM_WOUT  222336      // 96 floats
#define SM_RED   222720      // 4*64 floats = 1024B
#define SM_BOUT  223744
#define SMEM_BYTES 223760

__device__ __forceinline__ uint32_t cvt_tf32(float f) {
    uint32_t u;
    asm("cvt.rna.tf32.f32 %0, %1;" : "=r"(u) : "f"(f));
    return u;
}
__device__ __forceinline__ float leaky(float x) {
    return fmaxf(x, 0.0f) + 0.01f * fminf(x, 0.0f);
}
__device__ __forceinline__ void mma_tf32(float* d, uint32_t a0, uint32_t a1,
                                         uint32_t a2, uint32_t a3,
                                         uint32_t b0, uint32_t b1) {
    asm volatile(
        "mma.sync.aligned.m16n8k8.row.col.f32.tf32.tf32.f32 "
        "{%0,%1,%2,%3}, {%4,%5,%6,%7}, {%8,%9}, {%0,%1,%2,%3};"
        : "+f"(d[0]), "+f"(d[1]), "+f"(d[2]), "+f"(d[3])
        : "r"(a0), "r"(a1), "r"(a2), "r"(a3), "r"(b0), "r"(b1));
}

__global__ void __launch_bounds__(THREADS, 1) edgenet_mma_kernel(
    const float* __restrict__ feat,
    const float* __restrict__ W0, const float* __restrict__ g0,
    const float* __restrict__ b0, const float* __restrict__ m0,
    const float* __restrict__ v0,
    const float* __restrict__ W1, const float* __restrict__ g1,
    const float* __restrict__ b1, const float* __restrict__ m1,
    const float* __restrict__ v1,
    const float* __restrict__ Wout, const float* __restrict__ bout,
    float* __restrict__ sim_out)
{
    extern __shared__ char smem[];
    uint2*  W0F   = (uint2*)(smem + SM_W0F);
    uint2*  W1F   = (uint2*)(smem + SM_W1F);
    uint2*  XHF   = (uint2*)(smem + SM_XH);
    uint32_t* XHw = (uint32_t*)(smem + SM_XH);
    float*  bn0S  = (float*)(smem + SM_BN0);
    float*  bn1S  = (float*)(smem + SM_BN1);
    float*  woutS = (float*)(smem + SM_WOUT);
    float*  redS  = (float*)(smem + SM_RED);
    float*  boutS = (float*)(smem + SM_BOUT);

    const int tid  = threadIdx.x;
    const int wid  = tid >> 5;
    const int lane = tid & 31;
    const int g    = lane >> 2;   // group id (0..7)
    const int t4   = lane & 3;    // thread-in-group

    // ---- stage weights ONCE (BN scale folded into W; shift kept separate) ----
    for (int idx = tid; idx < H0C * FF; idx += THREADS) {
        int c = idx >> 7, f = idx & 127;
        float s = g0[c] * rsqrtf(v0[c] + 1e-5f);
        uint32_t bits = cvt_tf32(W0[idx] * s);
        int word = ((((c >> 3) * 16 + (f >> 3)) * 32 + (c & 7) * 4 + (f & 3)) << 1)
                   + ((f >> 2) & 1);
        ((uint32_t*)W0F)[word] = bits;
    }
    for (int idx = tid; idx < H1C * H0C; idx += THREADS) {
        int d = idx / H0C, c = idx - d * H0C;
        float s = g1[d] * rsqrtf(v1[d] + 1e-5f);
        uint32_t bits = cvt_tf32(W1[idx] * s);
        int word = ((((d >> 3) * 24 + (c >> 3)) * 32 + (d & 7) * 4 + (c & 3)) << 1)
                   + ((c >> 2) & 1);
        ((uint32_t*)W1F)[word] = bits;
    }
    for (int c = tid; c < H0C; c += THREADS) {
        float s = g0[c] * rsqrtf(v0[c] + 1e-5f);
        bn0S[c] = b0[c] - m0[c] * s;
    }
    for (int d = tid; d < H1C; d += THREADS) {
        float s = g1[d] * rsqrtf(v1[d] + 1e-5f);
        bn1S[d] = b1[d] - m1[d] * s;
        woutS[d] = Wout[d];
    }
    if (tid == 0) boutS[0] = bout[0];
    __syncthreads();
    const float boutv = boutS[0];

    // warp roles
    const int wm  = wid & 1;      // GEMM1: M half (32 rows)
    const int wn  = wid >> 1;     // GEMM1: N quarter (48 ch)
    const int wm2 = wid & 1;      // GEMM2: M half
    const int wn2 = wid >> 1;     // GEMM2: N quarter (24 ch)

    // buildX thread mapping: 4 threads per row, each covers 32 feats
    const int xrow = tid >> 2;    // 0..63
    const int xq   = tid & 3;     // feature quarter

    for (int t = blockIdx.x; t < TILES; t += GRIDX) {
        const int i  = t & 1023;
        const int jb = t >> 10;

        // ---------- build X fragments: X[p][f] = |feat[i][f]-feat[jb*64+p][f]| ----------
        {
            const float4* fi = (const float4*)(feat + i * FF + xq * 32);
            const float4* fj = (const float4*)(feat + (jb * 64 + xrow) * FF + xq * 32);
            const int mt   = xrow >> 4;
            const int half = (xrow >> 3) & 1;
            const int gg   = xrow & 7;
#pragma unroll
            for (int ktl = 0; ktl < 4; ++ktl) {
                float4 a0 = fi[ktl * 2], a1 = fi[ktl * 2 + 1];
                float4 c0 = fj[ktl * 2], c1 = fj[ktl * 2 + 1];
                uint2 u0, u1, u2, u3;
                u0.x = cvt_tf32(fabsf(a0.x - c0.x)); u0.y = cvt_tf32(fabsf(a1.x - c1.x));
                u1.x = cvt_tf32(fabsf(a0.y - c0.y)); u1.y = cvt_tf32(fabsf(a1.y - c1.y));
                u2.x = cvt_tf32(fabsf(a0.z - c0.z)); u2.y = cvt_tf32(fabsf(a1.z - c1.z));
                u3.x = cvt_tf32(fabsf(a0.w - c0.w)); u3.y = cvt_tf32(fabsf(a1.w - c1.w));
                int kt = xq * 4 + ktl;
                uint2* dst = &XHF[(mt * 16 + kt) * 64 + half * 32 + gg * 4];
                dst[0] = u0; dst[1] = u1; dst[2] = u2; dst[3] = u3;
            }
        }
        __syncthreads();

        // ---------- GEMM1: [64 x 192] = X[64 x 128] * W0'^T ----------
        float c1r[2][6][4];
#pragma unroll
        for (int mt = 0; mt < 2; ++mt)
#pragma unroll
            for (int nt = 0; nt < 6; ++nt)
#pragma unroll
                for (int r = 0; r < 4; ++r) c1r[mt][nt][r] = 0.0f;

#pragma unroll 4
        for (int kt = 0; kt < 16; ++kt) {
            uint2 a[2][2];
#pragma unroll
            for (int mt = 0; mt < 2; ++mt) {
                const uint2* ap = &XHF[((wm * 2 + mt) * 16 + kt) * 64 + lane];
                a[mt][0] = ap[0];
                a[mt][1] = ap[32];
            }
#pragma unroll
            for (int nt = 0; nt < 6; ++nt) {
                uint2 bf = W0F[((wn * 6 + nt) * 16 + kt) * 32 + lane];
#pragma unroll
                for (int mt = 0; mt < 2; ++mt)
                    mma_tf32(c1r[mt][nt], a[mt][0].x, a[mt][1].x, a[mt][0].y,
                             a[mt][1].y, bf.x, bf.y);
            }
        }
        __syncthreads();   // all GEMM1 reads of X done before H overwrites

        // ---------- epilogue1: BN shift + leaky -> H fragments (in XH region) ----------
#pragma unroll
        for (int mt = 0; mt < 2; ++mt) {
#pragma unroll
            for (int nt = 0; nt < 6; ++nt) {
                int col0 = wn * 48 + nt * 8 + 2 * t4;
                int r0   = (wm * 2 + mt) * 16 + g;
                float s0 = bn0S[col0], s1 = bn0S[col0 + 1];
                uint32_t h00 = cvt_tf32(leaky(c1r[mt][nt][0] + s0));
                uint32_t h01 = cvt_tf32(leaky(c1r[mt][nt][1] + s1));
                uint32_t h10 = cvt_tf32(leaky(c1r[mt][nt][2] + s0));
                uint32_t h11 = cvt_tf32(leaky(c1r[mt][nt][3] + s1));
                // scatter into H fragment order: addr(m, c)
                auto stH = [&](int m, int c, uint32_t bits) {
                    int word = ((((m >> 4) * 24 + (c >> 3)) * 64 + ((m >> 3) & 1) * 32
                                 + (m & 7) * 4 + (c & 3)) << 1) + ((c >> 2) & 1);
                    XHw[word] = bits;
                };
                stH(r0,     col0,     h00);
                stH(r0,     col0 + 1, h01);
                stH(r0 + 8, col0,     h10);
                stH(r0 + 8, col0 + 1, h11);
            }
        }
        __syncthreads();

        // ---------- GEMM2: [64 x 96] = H[64 x 192] * W1'^T ----------
        float c2r[2][3][4];
#pragma unroll
        for (int mt = 0; mt < 2; ++mt)
#pragma unroll
            for (int nt = 0; nt < 3; ++nt)
#pragma unroll
                for (int r = 0; r < 4; ++r) c2r[mt][nt][r] = 0.0f;

#pragma unroll 4
        for (int kt = 0; kt < 24; ++kt) {
            uint2 a[2][2];
#pragma unroll
            for (int mt = 0; mt < 2; ++mt) {
                const uint2* ap = &XHF[((wm2 * 2 + mt) * 24 + kt) * 64 + lane];
                a[mt][0] = ap[0];
                a[mt][1] = ap[32];
            }
#pragma unroll
            for (int nt = 0; nt < 3; ++nt) {
                uint2 bf = W1F[((wn2 * 3 + nt) * 24 + kt) * 32 + lane];
#pragma unroll
                for (int mt = 0; mt < 2; ++mt)
                    mma_tf32(c2r[mt][nt], a[mt][0].x, a[mt][1].x, a[mt][0].y,
                             a[mt][1].y, bf.x, bf.y);
            }
        }

        // ---------- epilogue2: BN shift + leaky + Wout dot + reduce ----------
#pragma unroll
        for (int mt = 0; mt < 2; ++mt) {
#pragma unroll
            for (int half = 0; half < 2; ++half) {
                float acc = 0.0f;
#pragma unroll
                for (int nt = 0; nt < 3; ++nt) {
                    int col0 = wn2 * 24 + nt * 8 + 2 * t4;
                    float h0 = leaky(c2r[mt][nt][half * 2 + 0] + bn1S[col0]);
                    float h1 = leaky(c2r[mt][nt][half * 2 + 1] + bn1S[col0 + 1]);
                    acc += woutS[col0] * h0 + woutS[col0 + 1] * h1;
                }
                acc += __shfl_xor_sync(0xffffffffu, acc, 1);
                acc += __shfl_xor_sync(0xffffffffu, acc, 2);
                if (t4 == 0) {
                    int row = (wm2 * 2 + mt) * 16 + half * 8 + g;
                    redS[wn2 * 64 + row] = acc;
                }
            }
        }
        __syncthreads();
        if (tid < 64) {
            float logit = redS[tid] + redS[64 + tid] + redS[128 + tid]
                        + redS[192 + tid] + boutv;
            float s = 1.0f / (1.0f + __expf(-logit));
            sim_out[i * NN + jb * 64 + tid] = s;
        }
        __syncthreads();   // protect redS + XH region before next tile
    }
}

// ---- pass 2: partial column sums of sim over 128-row slabs ----
__device__ float g_colpart[8][NN];

__global__ void colsum_kernel(const float* __restrict__ sim) {
    int j = blockIdx.x * 256 + threadIdx.x;
    int slab = blockIdx.y;
    float s = 0.0f;
    int ibase = slab * 128;
#pragma unroll 8
    for (int i = 0; i < 128; ++i) s += sim[(ibase + i) * NN + j];
    g_colpart[slab][j] = s;
}

// ---- pass 3: edge = (sim + eye + 1e-6) / colsum_over_i ----
__global__ void edge_kernel(const float* __restrict__ sim, float* __restrict__ edge) {
    int idx = blockIdx.x * 256 + threadIdx.x;
    int i = idx >> 10;
    int j = idx & (NN - 1);
    float denom = 1.0f + NN * 1e-6f;
#pragma unroll
    for (int r = 0; r < 8; ++r) denom += g_colpart[r][j];
    float v = sim[idx] + ((i == j) ? 1.0f : 0.0f) + 1e-6f;
    edge[idx] = v / denom;
}

extern "C" void kernel_launch(void* const* d_in, const int* in_sizes, int n_in,
                              void* d_out, int out_size) {
    const float* feat = (const float*)d_in[0];
    const float* W0   = (const float*)d_in[1];
    const float* g0   = (const float*)d_in[2];
    const float* b0   = (const float*)d_in[3];
    const float* m0   = (const float*)d_in[4];
    const float* v0   = (const float*)d_in[5];
    const float* W1   = (const float*)d_in[6];
    const float* g1   = (const float*)d_in[7];
    const float* b1   = (const float*)d_in[8];
    const float* m1   = (const float*)d_in[9];
    const float* v1   = (const float*)d_in[10];
    const float* Wout = (const float*)d_in[11];
    const float* bout = (const float*)d_in[12];

    float* out  = (float*)d_out;
    float* edge = out;              // edge_feat [1,N,N] first
    float* sim  = out + NN * NN;    // sim_val [N,N] second

    cudaFuncSetAttribute(edgenet_mma_kernel,
                         cudaFuncAttributeMaxDynamicSharedMemorySize, SMEM_BYTES);

    edgenet_mma_kernel<<<GRIDX, THREADS, SMEM_BYTES>>>(
        feat, W0, g0, b0, m0, v0, W1, g1, b1, m1, v1, Wout, bout, sim);

    colsum_kernel<<<dim3(4, 8), 256>>>(sim);
    edge_kernel<<<(NN * NN) / 256, 256>>>(sim, edge);
}

// round 6
// speedup vs baseline: 2.6894x; 1.0549x over previous
#include <cuda_runtime.h>
#include <math.h>
#include <cstdint>

#define NN 1024
#define FF 128
#define H0C 192
#define H1C 96
#define THREADS 256
#define GRIDX 148
#define TILES 16384          // 1024 i  x  16 j-blocks of 64

// ---------------- SMEM layout (bytes) ----------------
#define SM_W0F   0
#define SM_W1F   98304
#define SM_XH    172032
#define SM_BN0   221184      // 192 floats
#define SM_BN1   221952      // 96 floats
#define SM_WOUT  222336      // 96 floats
#define SM_RED   222720      // 4*64 floats
#define SM_BOUT  223744
#define SMEM_BYTES 223760

__device__ __forceinline__ uint32_t cvt_tf32(float f) {
    uint32_t u;
    asm("cvt.rna.tf32.f32 %0, %1;" : "=r"(u) : "f"(f));
    return u;
}
__device__ __forceinline__ float leaky(float x) {
    return fmaxf(x, 0.0f) + 0.01f * fminf(x, 0.0f);
}
__device__ __forceinline__ void mma_tf32(float* d, uint32_t a0, uint32_t a1,
                                         uint32_t a2, uint32_t a3,
                                         uint32_t b0, uint32_t b1) {
    asm volatile(
        "mma.sync.aligned.m16n8k8.row.col.f32.tf32.tf32.f32 "
        "{%0,%1,%2,%3}, {%4,%5,%6,%7}, {%8,%9}, {%0,%1,%2,%3};"
        : "+f"(d[0]), "+f"(d[1]), "+f"(d[2]), "+f"(d[3])
        : "r"(a0), "r"(a1), "r"(a2), "r"(a3), "r"(b0), "r"(b1));
}

__global__ void __launch_bounds__(THREADS, 1) edgenet_mma_kernel(
    const float* __restrict__ feat,
    const float* __restrict__ W0, const float* __restrict__ g0,
    const float* __restrict__ b0, const float* __restrict__ m0,
    const float* __restrict__ v0,
    const float* __restrict__ W1, const float* __restrict__ g1,
    const float* __restrict__ b1, const float* __restrict__ m1,
    const float* __restrict__ v1,
    const float* __restrict__ Wout, const float* __restrict__ bout,
    float* __restrict__ sim_out)
{
    extern __shared__ char smem[];
    uint2*  W0F   = (uint2*)(smem + SM_W0F);
    uint2*  W1F   = (uint2*)(smem + SM_W1F);
    uint2*  XHF   = (uint2*)(smem + SM_XH);
    uint32_t* XHw = (uint32_t*)(smem + SM_XH);
    float*  bn0S  = (float*)(smem + SM_BN0);
    float*  bn1S  = (float*)(smem + SM_BN1);
    float*  woutS = (float*)(smem + SM_WOUT);
    float*  redS  = (float*)(smem + SM_RED);
    float*  boutS = (float*)(smem + SM_BOUT);

    const int tid  = threadIdx.x;
    const int wid  = tid >> 5;
    const int lane = tid & 31;
    const int g    = lane >> 2;   // group id (0..7)
    const int t4   = lane & 3;    // thread-in-group

    // ---- stage weights ONCE (BN scale folded into W; shift separate) ----
    for (int idx = tid; idx < H0C * FF; idx += THREADS) {
        int c = idx >> 7, f = idx & 127;
        float s = g0[c] * rsqrtf(v0[c] + 1e-5f);
        uint32_t bits = cvt_tf32(W0[idx] * s);
        int word = ((((c >> 3) * 16 + (f >> 3)) * 32 + (c & 7) * 4 + (f & 3)) << 1)
                   + ((f >> 2) & 1);
        ((uint32_t*)W0F)[word] = bits;
    }
    for (int idx = tid; idx < H1C * H0C; idx += THREADS) {
        int d = idx / H0C, c = idx - d * H0C;
        float s = g1[d] * rsqrtf(v1[d] + 1e-5f);
        uint32_t bits = cvt_tf32(W1[idx] * s);
        int word = ((((d >> 3) * 24 + (c >> 3)) * 32 + (d & 7) * 4 + (c & 3)) << 1)
                   + ((c >> 2) & 1);
        ((uint32_t*)W1F)[word] = bits;
    }
    for (int c = tid; c < H0C; c += THREADS) {
        float s = g0[c] * rsqrtf(v0[c] + 1e-5f);
        bn0S[c] = b0[c] - m0[c] * s;
    }
    for (int d = tid; d < H1C; d += THREADS) {
        float s = g1[d] * rsqrtf(v1[d] + 1e-5f);
        bn1S[d] = b1[d] - m1[d] * s;
        woutS[d] = Wout[d];
    }
    if (tid == 0) boutS[0] = bout[0];
    __syncthreads();
    const float boutv = boutS[0];

    // warp roles
    const int wm = wid & 1;      // M half (32 rows)
    const int wn = wid >> 1;     // N quarter (48 ch GEMM1 / 24 ch GEMM2)

    // ---- cross-tile register cache: W0 B-frags for nt=0..2 (96 regs) ----
    uint2 w0c[16][3];
#pragma unroll
    for (int kt = 0; kt < 16; ++kt)
#pragma unroll
        for (int c = 0; c < 3; ++c)
            w0c[kt][c] = W0F[((wn * 6 + c) * 16 + kt) * 32 + lane];

    // buildX thread mapping: 4 threads per row, each covers 32 feats
    const int xrow = tid >> 2;    // 0..63
    const int xq   = tid & 3;     // feature quarter

    for (int t = blockIdx.x; t < TILES; t += GRIDX) {
        const int i  = t & 1023;
        const int jb = t >> 10;

        // ---------- build X fragments ----------
        {
            const float4* fi = (const float4*)(feat + i * FF + xq * 32);
            const float4* fj = (const float4*)(feat + (jb * 64 + xrow) * FF + xq * 32);
            const int mt   = xrow >> 4;
            const int half = (xrow >> 3) & 1;
            const int gg   = xrow & 7;
#pragma unroll
            for (int ktl = 0; ktl < 4; ++ktl) {
                float4 a0 = fi[ktl * 2], a1 = fi[ktl * 2 + 1];
                float4 c0 = fj[ktl * 2], c1 = fj[ktl * 2 + 1];
                uint2 u0, u1, u2, u3;
                u0.x = cvt_tf32(fabsf(a0.x - c0.x)); u0.y = cvt_tf32(fabsf(a1.x - c1.x));
                u1.x = cvt_tf32(fabsf(a0.y - c0.y)); u1.y = cvt_tf32(fabsf(a1.y - c1.y));
                u2.x = cvt_tf32(fabsf(a0.z - c0.z)); u2.y = cvt_tf32(fabsf(a1.z - c1.z));
                u3.x = cvt_tf32(fabsf(a0.w - c0.w)); u3.y = cvt_tf32(fabsf(a1.w - c1.w));
                int kt = xq * 4 + ktl;
                uint2* dst = &XHF[(mt * 16 + kt) * 64 + half * 32 + gg * 4];
                dst[0] = u0; dst[1] = u1; dst[2] = u2; dst[3] = u3;
            }
        }
        __syncthreads();

        // ---------- GEMM1: [64 x 192] = X[64 x 128] * W0'^T (pipelined) ----------
        float c1r[2][6][4];
#pragma unroll
        for (int mt = 0; mt < 2; ++mt)
#pragma unroll
            for (int nt = 0; nt < 6; ++nt)
#pragma unroll
                for (int r = 0; r < 4; ++r) c1r[mt][nt][r] = 0.0f;

        uint2 a[2][2], bs[3];
#pragma unroll
        for (int mt = 0; mt < 2; ++mt) {
            const uint2* ap = &XHF[((wm * 2 + mt) * 16 + 0) * 64 + lane];
            a[mt][0] = ap[0]; a[mt][1] = ap[32];
        }
#pragma unroll
        for (int j = 0; j < 3; ++j)
            bs[j] = W0F[((wn * 6 + 3 + j) * 16 + 0) * 32 + lane];

#pragma unroll
        for (int kt = 0; kt < 16; ++kt) {
            uint2 an[2][2], bn[3];
            if (kt < 15) {
#pragma unroll
                for (int mt = 0; mt < 2; ++mt) {
                    const uint2* ap = &XHF[((wm * 2 + mt) * 16 + kt + 1) * 64 + lane];
                    an[mt][0] = ap[0]; an[mt][1] = ap[32];
                }
#pragma unroll
                for (int j = 0; j < 3; ++j)
                    bn[j] = W0F[((wn * 6 + 3 + j) * 16 + kt + 1) * 32 + lane];
            }
#pragma unroll
            for (int nt = 0; nt < 3; ++nt)
#pragma unroll
                for (int mt = 0; mt < 2; ++mt)
                    mma_tf32(c1r[mt][nt], a[mt][0].x, a[mt][1].x, a[mt][0].y,
                             a[mt][1].y, w0c[kt][nt].x, w0c[kt][nt].y);
#pragma unroll
            for (int nt = 3; nt < 6; ++nt)
#pragma unroll
                for (int mt = 0; mt < 2; ++mt)
                    mma_tf32(c1r[mt][nt], a[mt][0].x, a[mt][1].x, a[mt][0].y,
                             a[mt][1].y, bs[nt - 3].x, bs[nt - 3].y);
            if (kt < 15) {
#pragma unroll
                for (int mt = 0; mt < 2; ++mt) {
                    a[mt][0] = an[mt][0]; a[mt][1] = an[mt][1];
                }
#pragma unroll
                for (int j = 0; j < 3; ++j) bs[j] = bn[j];
            }
        }
        __syncthreads();   // all GEMM1 reads of X done before H overwrites

        // ---------- epilogue1: BN shift + leaky -> H fragments ----------
#pragma unroll
        for (int mt = 0; mt < 2; ++mt) {
#pragma unroll
            for (int nt = 0; nt < 6; ++nt) {
                int col0 = wn * 48 + nt * 8 + 2 * t4;
                int r0   = (wm * 2 + mt) * 16 + g;
                float s0 = bn0S[col0], s1 = bn0S[col0 + 1];
                uint32_t h00 = cvt_tf32(leaky(c1r[mt][nt][0] + s0));
                uint32_t h01 = cvt_tf32(leaky(c1r[mt][nt][1] + s1));
                uint32_t h10 = cvt_tf32(leaky(c1r[mt][nt][2] + s0));
                uint32_t h11 = cvt_tf32(leaky(c1r[mt][nt][3] + s1));
                auto stH = [&](int m, int c, uint32_t bits) {
                    int word = ((((m >> 4) * 24 + (c >> 3)) * 64 + ((m >> 3) & 1) * 32
                                 + (m & 7) * 4 + (c & 3)) << 1) + ((c >> 2) & 1);
                    XHw[word] = bits;
                };
                stH(r0,     col0,     h00);
                stH(r0,     col0 + 1, h01);
                stH(r0 + 8, col0,     h10);
                stH(r0 + 8, col0 + 1, h11);
            }
        }
        __syncthreads();

        // ---------- GEMM2: [64 x 96] = H[64 x 192] * W1'^T (pipelined) ----------
        float c2r[2][3][4];
#pragma unroll
        for (int mt = 0; mt < 2; ++mt)
#pragma unroll
            for (int nt = 0; nt < 3; ++nt)
#pragma unroll
                for (int r = 0; r < 4; ++r) c2r[mt][nt][r] = 0.0f;

        uint2 a2[2][2], b2[3];
#pragma unroll
        for (int mt = 0; mt < 2; ++mt) {
            const uint2* ap = &XHF[((wm * 2 + mt) * 24 + 0) * 64 + lane];
            a2[mt][0] = ap[0]; a2[mt][1] = ap[32];
        }
#pragma unroll
        for (int j = 0; j < 3; ++j)
            b2[j] = W1F[((wn * 3 + j) * 24 + 0) * 32 + lane];

#pragma unroll
        for (int kt = 0; kt < 24; ++kt) {
            uint2 an[2][2], bn[3];
            if (kt < 23) {
#pragma unroll
                for (int mt = 0; mt < 2; ++mt) {
                    const uint2* ap = &XHF[((wm * 2 + mt) * 24 + kt + 1) * 64 + lane];
                    an[mt][0] = ap[0]; an[mt][1] = ap[32];
                }
#pragma unroll
                for (int j = 0; j < 3; ++j)
                    bn[j] = W1F[((wn * 3 + j) * 24 + kt + 1) * 32 + lane];
            }
#pragma unroll
            for (int nt = 0; nt < 3; ++nt)
#pragma unroll
                for (int mt = 0; mt < 2; ++mt)
                    mma_tf32(c2r[mt][nt], a2[mt][0].x, a2[mt][1].x, a2[mt][0].y,
                             a2[mt][1].y, b2[nt].x, b2[nt].y);
            if (kt < 23) {
#pragma unroll
                for (int mt = 0; mt < 2; ++mt) {
                    a2[mt][0] = an[mt][0]; a2[mt][1] = an[mt][1];
                }
#pragma unroll
                for (int j = 0; j < 3; ++j) b2[j] = bn[j];
            }
        }

        // ---------- epilogue2: BN shift + leaky + Wout dot + reduce ----------
#pragma unroll
        for (int mt = 0; mt < 2; ++mt) {
#pragma unroll
            for (int half = 0; half < 2; ++half) {
                float acc = 0.0f;
#pragma unroll
                for (int nt = 0; nt < 3; ++nt) {
                    int col0 = wn * 24 + nt * 8 + 2 * t4;
                    float h0 = leaky(c2r[mt][nt][half * 2 + 0] + bn1S[col0]);
                    float h1 = leaky(c2r[mt][nt][half * 2 + 1] + bn1S[col0 + 1]);
                    acc += woutS[col0] * h0 + woutS[col0 + 1] * h1;
                }
                acc += __shfl_xor_sync(0xffffffffu, acc, 1);
                acc += __shfl_xor_sync(0xffffffffu, acc, 2);
                if (t4 == 0) {
                    int row = (wm * 2 + mt) * 16 + half * 8 + g;
                    redS[wn * 64 + row] = acc;
                }
            }
        }
        __syncthreads();
        if (tid < 64) {
            float logit = redS[tid] + redS[64 + tid] + redS[128 + tid]
                        + redS[192 + tid] + boutv;
            float s = 1.0f / (1.0f + __expf(-logit));
            sim_out[i * NN + jb * 64 + tid] = s;
        }
        __syncthreads();   // protect redS + XH region before next tile
    }
}

// ---- pass 2: partial column sums of sim over 128-row slabs ----
__device__ float g_colpart[8][NN];

__global__ void colsum_kernel(const float* __restrict__ sim) {
    int j = blockIdx.x * 256 + threadIdx.x;
    int slab = blockIdx.y;
    float s = 0.0f;
    int ibase = slab * 128;
#pragma unroll 8
    for (int i = 0; i < 128; ++i) s += sim[(ibase + i) * NN + j];
    g_colpart[slab][j] = s;
}

// ---- pass 3: edge = (sim + eye + 1e-6) / colsum_over_i ----
__global__ void edge_kernel(const float* __restrict__ sim, float* __restrict__ edge) {
    int idx = blockIdx.x * 256 + threadIdx.x;
    int i = idx >> 10;
    int j = idx & (NN - 1);
    float denom = 1.0f + NN * 1e-6f;
#pragma unroll
    for (int r = 0; r < 8; ++r) denom += g_colpart[r][j];
    float v = sim[idx] + ((i == j) ? 1.0f : 0.0f) + 1e-6f;
    edge[idx] = v / denom;
}

extern "C" void kernel_launch(void* const* d_in, const int* in_sizes, int n_in,
                              void* d_out, int out_size) {
    const float* feat = (const float*)d_in[0];
    const float* W0   = (const float*)d_in[1];
    const float* g0   = (const float*)d_in[2];
    const float* b0   = (const float*)d_in[3];
    const float* m0   = (const float*)d_in[4];
    const float* v0   = (const float*)d_in[5];
    const float* W1   = (const float*)d_in[6];
    const float* g1   = (const float*)d_in[7];
    const float* b1   = (const float*)d_in[8];
    const float* m1   = (const float*)d_in[9];
    const float* v1   = (const float*)d_in[10];
    const float* Wout = (const float*)d_in[11];
    const float* bout = (const float*)d_in[12];

    float* out  = (float*)d_out;
    float* edge = out;              // edge_feat [1,N,N] first
    float* sim  = out + NN * NN;    // sim_val [N,N] second

    cudaFuncSetAttribute(edgenet_mma_kernel,
                         cudaFuncAttributeMaxDynamicSharedMemorySize, SMEM_BYTES);

    edgenet_mma_kernel<<<GRIDX, THREADS, SMEM_BYTES>>>(
        feat, W0, g0, b0, m0, v0, W1, g1, b1, m1, v1, Wout, bout, sim);

    colsum_kernel<<<dim3(4, 8), 256>>>(sim);
    edge_kernel<<<(NN * NN) / 256, 256>>>(sim, edge);
}

// round 7
// speedup vs baseline: 6.8118x; 2.5328x over previous
#include <cuda_runtime.h>
#include <math.h>
#include <cstdint>

#define NN 1024
#define FF 128
#define H0C 192
#define H1C 96
#define THREADS 512
#define GRIDX 148
#define TILES 8192           // 1024 i  x  8 j-blocks of 128

// ---------------- SMEM layout (bytes) ----------------
// W0F: [24 nt][8 kt][32 lanes] uint2 = 49152
// W1F: [12 nt][12 kt][32] uint2     = 36864
// XF:  [8 mt][8 kt] frags, 33 uint4 stride = 2112 uint4 = 33792
// HF:  [8 mt][12 kt][32] uint4      = 49152
#define SM_W0F   0
#define SM_W1F   49152
#define SM_XF    86016
#define SM_HF    119808
#define SM_BN0   168960      // 192 floats
#define SM_BN1   169728      // 96 floats
#define SM_WOUT  170112      // 96 floats
#define SM_RED   170496      // 4*128 floats
#define SM_BOUT  172544
#define SMEM_BYTES 172560

__device__ __forceinline__ uint32_t pack_bf16x2(float lo, float hi) {
    uint32_t r;
    asm("cvt.rn.bf16x2.f32 %0, %1, %2;" : "=r"(r) : "f"(hi), "f"(lo));
    return r;
}
__device__ __forceinline__ float leaky(float x) {
    return fmaxf(x, 0.0f) + 0.01f * fminf(x, 0.0f);
}
__device__ __forceinline__ void mma_bf16(float* d, const uint32_t* a,
                                         uint32_t b0, uint32_t b1) {
    asm volatile(
        "mma.sync.aligned.m16n8k16.row.col.f32.bf16.bf16.f32 "
        "{%0,%1,%2,%3}, {%4,%5,%6,%7}, {%8,%9}, {%0,%1,%2,%3};"
        : "+f"(d[0]), "+f"(d[1]), "+f"(d[2]), "+f"(d[3])
        : "r"(a[0]), "r"(a[1]), "r"(a[2]), "r"(a[3]), "r"(b0), "r"(b1));
}

__global__ void __launch_bounds__(THREADS, 1) edgenet_bf16_kernel(
    const float* __restrict__ feat,
    const float* __restrict__ W0, const float* __restrict__ g0,
    const float* __restrict__ b0, const float* __restrict__ m0,
    const float* __restrict__ v0,
    const float* __restrict__ W1, const float* __restrict__ g1,
    const float* __restrict__ b1, const float* __restrict__ m1,
    const float* __restrict__ v1,
    const float* __restrict__ Wout, const float* __restrict__ bout,
    float* __restrict__ sim_out)
{
    extern __shared__ char smem[];
    uint2*    W0F  = (uint2*)(smem + SM_W0F);
    uint2*    W1F  = (uint2*)(smem + SM_W1F);
    uint4*    XF4  = (uint4*)(smem + SM_XF);
    uint32_t* Xw   = (uint32_t*)(smem + SM_XF);
    uint4*    HF4  = (uint4*)(smem + SM_HF);
    uint32_t* Hw   = (uint32_t*)(smem + SM_HF);
    float*    bn0S = (float*)(smem + SM_BN0);
    float*    bn1S = (float*)(smem + SM_BN1);
    float*    woutS= (float*)(smem + SM_WOUT);
    float*    redS = (float*)(smem + SM_RED);
    float*    boutS= (float*)(smem + SM_BOUT);

    const int tid  = threadIdx.x;
    const int wid  = tid >> 5;
    const int lane = tid & 31;
    const int g    = lane >> 2;
    const int t4   = lane & 3;

    // ---- stage weights ONCE as bf16 B-fragments (BN scale folded) ----
    for (int idx = tid; idx < 24 * 8 * 32; idx += THREADS) {
        int ntg = idx >> 8, kt = (idx >> 5) & 7, ln = idx & 31;
        int c = ntg * 8 + (ln >> 2);
        int f = kt * 16 + (ln & 3) * 2;
        float s = g0[c] * rsqrtf(v0[c] + 1e-5f);
        uint2 b;
        b.x = pack_bf16x2(W0[c * FF + f] * s,     W0[c * FF + f + 1] * s);
        b.y = pack_bf16x2(W0[c * FF + f + 8] * s, W0[c * FF + f + 9] * s);
        W0F[idx] = b;
    }
    for (int idx = tid; idx < 12 * 12 * 32; idx += THREADS) {
        int ntg = idx / 384, kt = (idx / 32) % 12, ln = idx & 31;
        int d = ntg * 8 + (ln >> 2);
        int k = kt * 16 + (ln & 3) * 2;
        float s = g1[d] * rsqrtf(v1[d] + 1e-5f);
        uint2 b;
        b.x = pack_bf16x2(W1[d * H0C + k] * s,     W1[d * H0C + k + 1] * s);
        b.y = pack_bf16x2(W1[d * H0C + k + 8] * s, W1[d * H0C + k + 9] * s);
        W1F[idx] = b;
    }
    for (int c = tid; c < H0C; c += THREADS) {
        float s = g0[c] * rsqrtf(v0[c] + 1e-5f);
        bn0S[c] = b0[c] - m0[c] * s;
    }
    for (int d = tid; d < H1C; d += THREADS) {
        float s = g1[d] * rsqrtf(v1[d] + 1e-5f);
        bn1S[d] = b1[d] - m1[d] * s;
        woutS[d] = Wout[d];
    }
    if (tid == 0) boutS[0] = bout[0];
    __syncthreads();
    const float boutv = boutS[0];

    // warp roles: 4 m-groups x 4 n-groups
    const int wm = wid & 3;     // rows wm*32 .. +31  (2 mt of 16)
    const int wn = wid >> 2;    // GEMM1: 48 ch, GEMM2: 24 ch

    // buildX constants (per pair-slot this lane writes)
    const int bx_kt  = lane >> 2;
    const int bx_pl0 = (2 * lane) & 7;            // 0,2,4,6
    const int bx_w0  = (bx_pl0 & 3) * 4;          // lane-slot offset (t4*4)
    const int bx_ph0 = (bx_pl0 >> 2) * 2;
    const int bx_w1  = ((bx_pl0 + 1) & 3) * 4;
    const int bx_ph1 = ((bx_pl0 + 1) >> 2) * 2;

    for (int t = blockIdx.x; t < TILES; t += GRIDX) {
        const int i  = t & 1023;
        const int jb = t >> 10;

        // ---------- buildX: warp-cooperative, 1 row per step ----------
        {
            const float4 fi4 = ((const float4*)(feat + i * FF))[lane];
#pragma unroll
            for (int rr = 0; rr < 8; ++rr) {
                int p = wid * 8 + rr;
                float4 fj4 = ((const float4*)(feat + (jb * 128 + p) * FF))[lane];
                float x0 = fabsf(fi4.x - fj4.x);
                float x1 = fabsf(fi4.y - fj4.y);
                float x2 = fabsf(fi4.z - fj4.z);
                float x3 = fabsf(fi4.w - fj4.w);
                uint32_t wA = pack_bf16x2(x0, x1);
                uint32_t wB = pack_bf16x2(x2, x3);
                int mt = p >> 4, r16 = p & 15;
                int gg = r16 & 7, rowbit = r16 >> 3;
                int base = ((mt * 8 + bx_kt) * 33 + gg * 4) * 4;
                Xw[base + bx_w0 + bx_ph0 + rowbit] = wA;
                Xw[base + bx_w1 + bx_ph1 + rowbit] = wB;
            }
        }
        __syncthreads();

        // ---------- GEMM1: [128 x 192] = X[128 x 128] * W0'^T ----------
        float c1r[2][6][4];
#pragma unroll
        for (int mt = 0; mt < 2; ++mt)
#pragma unroll
            for (int nt = 0; nt < 6; ++nt)
#pragma unroll
                for (int r = 0; r < 4; ++r) c1r[mt][nt][r] = 0.0f;

#pragma unroll
        for (int kt = 0; kt < 8; ++kt) {
            uint4 a[2];
#pragma unroll
            for (int mt = 0; mt < 2; ++mt)
                a[mt] = XF4[((wm * 2 + mt) * 8 + kt) * 33 + lane];
#pragma unroll
            for (int nt = 0; nt < 6; ++nt) {
                uint2 b = W0F[((wn * 6 + nt) * 8 + kt) * 32 + lane];
#pragma unroll
                for (int mt = 0; mt < 2; ++mt)
                    mma_bf16(c1r[mt][nt], (const uint32_t*)&a[mt], b.x, b.y);
            }
        }

        // ---------- epilogue1: BN shift + leaky -> H A-fragments (bf16) ----------
#pragma unroll
        for (int mt = 0; mt < 2; ++mt) {
            int mtg = wm * 2 + mt;
#pragma unroll
            for (int nt = 0; nt < 6; ++nt) {
                int col0 = wn * 48 + nt * 8 + 2 * t4;
                float s0 = bn0S[col0], s1 = bn0S[col0 + 1];
                uint32_t lo = pack_bf16x2(leaky(c1r[mt][nt][0] + s0),
                                          leaky(c1r[mt][nt][1] + s1));
                uint32_t hi = pack_bf16x2(leaky(c1r[mt][nt][2] + s0),
                                          leaky(c1r[mt][nt][3] + s1));
                int kt2  = (wn * 6 + nt) >> 1;
                int widx = (nt & 1) * 2;
                int base = ((mtg * 12 + kt2) * 32 + lane) * 4;
                Hw[base + widx]     = lo;   // row g
                Hw[base + widx + 1] = hi;   // row g+8
            }
        }
        __syncthreads();

        // ---------- GEMM2: [128 x 96] = H[128 x 192] * W1'^T ----------
        float c2r[2][3][4];
#pragma unroll
        for (int mt = 0; mt < 2; ++mt)
#pragma unroll
            for (int nt = 0; nt < 3; ++nt)
#pragma unroll
                for (int r = 0; r < 4; ++r) c2r[mt][nt][r] = 0.0f;

#pragma unroll
        for (int kt = 0; kt < 12; ++kt) {
            uint4 a[2];
#pragma unroll
            for (int mt = 0; mt < 2; ++mt)
                a[mt] = HF4[((wm * 2 + mt) * 12 + kt) * 32 + lane];
#pragma unroll
            for (int nt = 0; nt < 3; ++nt) {
                uint2 b = W1F[((wn * 3 + nt) * 12 + kt) * 32 + lane];
#pragma unroll
                for (int mt = 0; mt < 2; ++mt)
                    mma_bf16(c2r[mt][nt], (const uint32_t*)&a[mt], b.x, b.y);
            }
        }

        // ---------- epilogue2: BN shift + leaky + Wout dot + reduce ----------
#pragma unroll
        for (int mt = 0; mt < 2; ++mt) {
#pragma unroll
            for (int half = 0; half < 2; ++half) {
                float acc = 0.0f;
#pragma unroll
                for (int nt = 0; nt < 3; ++nt) {
                    int col0 = wn * 24 + nt * 8 + 2 * t4;
                    float h0 = leaky(c2r[mt][nt][half * 2 + 0] + bn1S[col0]);
                    float h1 = leaky(c2r[mt][nt][half * 2 + 1] + bn1S[col0 + 1]);
                    acc += woutS[col0] * h0 + woutS[col0 + 1] * h1;
                }
                acc += __shfl_xor_sync(0xffffffffu, acc, 1);
                acc += __shfl_xor_sync(0xffffffffu, acc, 2);
                if (t4 == 0) {
                    int row = (wm * 2 + mt) * 16 + half * 8 + g;
                    redS[wn * 128 + row] = acc;
                }
            }
        }
        __syncthreads();
        if (tid < 128) {
            float logit = redS[tid] + redS[128 + tid] + redS[256 + tid]
                        + redS[384 + tid] + boutv;
            float s = 1.0f / (1.0f + __expf(-logit));
            sim_out[i * NN + jb * 128 + tid] = s;
        }
        __syncthreads();   // protect redS + X frags before next tile
    }
}

// ---- pass 2: partial column sums of sim over 128-row slabs ----
__device__ float g_colpart[8][NN];

__global__ void colsum_kernel(const float* __restrict__ sim) {
    int j = blockIdx.x * 256 + threadIdx.x;
    int slab = blockIdx.y;
    float s = 0.0f;
    int ibase = slab * 128;
#pragma unroll 8
    for (int i = 0; i < 128; ++i) s += sim[(ibase + i) * NN + j];
    g_colpart[slab][j] = s;
}

// ---- pass 3: edge = (sim + eye + 1e-6) / colsum_over_i ----
__global__ void edge_kernel(const float* __restrict__ sim, float* __restrict__ edge) {
    int idx = blockIdx.x * 256 + threadIdx.x;
    int i = idx >> 10;
    int j = idx & (NN - 1);
    float denom = 1.0f + NN * 1e-6f;
#pragma unroll
    for (int r = 0; r < 8; ++r) denom += g_colpart[r][j];
    float v = sim[idx] + ((i == j) ? 1.0f : 0.0f) + 1e-6f;
    edge[idx] = v / denom;
}

extern "C" void kernel_launch(void* const* d_in, const int* in_sizes, int n_in,
                              void* d_out, int out_size) {
    const float* feat = (const float*)d_in[0];
    const float* W0   = (const float*)d_in[1];
    const float* g0   = (const float*)d_in[2];
    const float* b0   = (const float*)d_in[3];
    const float* m0   = (const float*)d_in[4];
    const float* v0   = (const float*)d_in[5];
    const float* W1   = (const float*)d_in[6];
    const float* g1   = (const float*)d_in[7];
    const float* b1   = (const float*)d_in[8];
    const float* m1   = (const float*)d_in[9];
    const float* v1   = (const float*)d_in[10];
    const float* Wout = (const float*)d_in[11];
    const float* bout = (const float*)d_in[12];

    float* out  = (float*)d_out;
    float* edge = out;              // edge_feat [1,N,N] first
    float* sim  = out + NN * NN;    // sim_val [N,N] second

    cudaFuncSetAttribute(edgenet_bf16_kernel,
                         cudaFuncAttributeMaxDynamicSharedMemorySize, SMEM_BYTES);

    edgenet_bf16_kernel<<<GRIDX, THREADS, SMEM_BYTES>>>(
        feat, W0, g0, b0, m0, v0, W1, g1, b1, m1, v1, Wout, bout, sim);

    colsum_kernel<<<dim3(4, 8), 256>>>(sim);
    edge_kernel<<<(NN * NN) / 256, 256>>>(sim, edge);
}

// round 9
// speedup vs baseline: 7.4824x; 1.0984x over previous
#include <cuda_runtime.h>
#include <math.h>
#include <cstdint>

#define NN 1024
#define FF 128
#define H0C 192
#define H1C 96
#define THREADS 512
#define GRIDX 148
#define TILES_SYM 4608       // sum over ib of 128*(8-ib)

// ---------------- SMEM layout (bytes) ----------------
#define SM_W0F   0
#define SM_W1F   49152
#define SM_XF    86016
#define SM_HF    119808
#define SM_BN0   168960      // 192 floats
#define SM_BN1   169728      // 96 floats
#define SM_WOUT  170112      // 96 floats
#define SM_RED   170496      // 4*128 floats
#define SM_BOUT  172544
#define SMEM_BYTES 172560

__device__ __forceinline__ uint32_t pack_bf16x2(float lo, float hi) {
    uint32_t r;
    asm("cvt.rn.bf16x2.f32 %0, %1, %2;" : "=r"(r) : "f"(hi), "f"(lo));
    return r;
}
__device__ __forceinline__ float leaky(float x) {
    return fmaxf(x, 0.0f) + 0.01f * fminf(x, 0.0f);
}
__device__ __forceinline__ void mma_bf16(float* d, const uint32_t* a,
                                         uint32_t b0, uint32_t b1) {
    asm volatile(
        "mma.sync.aligned.m16n8k16.row.col.f32.bf16.bf16.f32 "
        "{%0,%1,%2,%3}, {%4,%5,%6,%7}, {%8,%9}, {%0,%1,%2,%3};"
        : "+f"(d[0]), "+f"(d[1]), "+f"(d[2]), "+f"(d[3])
        : "r"(a[0]), "r"(a[1]), "r"(a[2]), "r"(a[3]), "r"(b0), "r"(b1));
}

__global__ void __launch_bounds__(THREADS, 1) edgenet_bf16_kernel(
    const float* __restrict__ feat,
    const float* __restrict__ W0, const float* __restrict__ g0,
    const float* __restrict__ b0, const float* __restrict__ m0,
    const float* __restrict__ v0,
    const float* __restrict__ W1, const float* __restrict__ g1,
    const float* __restrict__ b1, const float* __restrict__ m1,
    const float* __restrict__ v1,
    const float* __restrict__ Wout, const float* __restrict__ bout,
    float* __restrict__ sim_out)
{
    extern __shared__ char smem[];
    uint4*    W0F4 = (uint4*)(smem + SM_W0F);
    uint2*    W1F  = (uint2*)(smem + SM_W1F);
    uint4*    XF4  = (uint4*)(smem + SM_XF);
    uint32_t* Xw   = (uint32_t*)(smem + SM_XF);
    uint4*    HF4  = (uint4*)(smem + SM_HF);
    float*    bn0S = (float*)(smem + SM_BN0);
    float*    bn1S = (float*)(smem + SM_BN1);
    float*    woutS= (float*)(smem + SM_WOUT);
    float*    redS = (float*)(smem + SM_RED);
    float*    boutS= (float*)(smem + SM_BOUT);

    const int tid  = threadIdx.x;
    const int wid  = tid >> 5;
    const int lane = tid & 31;
    const int g    = lane >> 2;
    const int t4   = lane & 3;

    // ---- stage weights ONCE as bf16 B-fragments (BN scale folded) ----
    // W0 packed as uint4: q pairs channels (nt=2q, nt=2q+1)
    for (int idx = tid; idx < 12 * 8 * 32; idx += THREADS) {
        int q = idx >> 8, kt = (idx >> 5) & 7, ln = idx & 31;
        int c0 = (2 * q) * 8 + (ln >> 2);
        int c1 = c0 + 8;
        int f  = kt * 16 + (ln & 3) * 2;
        float s0 = g0[c0] * rsqrtf(v0[c0] + 1e-5f);
        float s1 = g0[c1] * rsqrtf(v0[c1] + 1e-5f);
        uint4 b;
        b.x = pack_bf16x2(W0[c0 * FF + f] * s0,     W0[c0 * FF + f + 1] * s0);
        b.y = pack_bf16x2(W0[c0 * FF + f + 8] * s0, W0[c0 * FF + f + 9] * s0);
        b.z = pack_bf16x2(W0[c1 * FF + f] * s1,     W0[c1 * FF + f + 1] * s1);
        b.w = pack_bf16x2(W0[c1 * FF + f + 8] * s1, W0[c1 * FF + f + 9] * s1);
        W0F4[idx] = b;
    }
    for (int idx = tid; idx < 12 * 12 * 32; idx += THREADS) {
        int ntg = idx / 384, kt = (idx / 32) % 12, ln = idx & 31;
        int d = ntg * 8 + (ln >> 2);
        int k = kt * 16 + (ln & 3) * 2;
        float s = g1[d] * rsqrtf(v1[d] + 1e-5f);
        uint2 b;
        b.x = pack_bf16x2(W1[d * H0C + k] * s,     W1[d * H0C + k + 1] * s);
        b.y = pack_bf16x2(W1[d * H0C + k + 8] * s, W1[d * H0C + k + 9] * s);
        W1F[idx] = b;
    }
    for (int c = tid; c < H0C; c += THREADS) {
        float s = g0[c] * rsqrtf(v0[c] + 1e-5f);
        bn0S[c] = b0[c] - m0[c] * s;
    }
    for (int d = tid; d < H1C; d += THREADS) {
        float s = g1[d] * rsqrtf(v1[d] + 1e-5f);
        bn1S[d] = b1[d] - m1[d] * s;
        woutS[d] = Wout[d];
    }
    if (tid == 0) boutS[0] = bout[0];
    __syncthreads();
    const float boutv = boutS[0];

    // warp roles: 4 m-groups x 4 n-groups
    const int wm = wid & 3;     // rows wm*32 .. +31  (2 mt of 16)
    const int wn = wid >> 2;    // GEMM1: 48 ch (3 q), GEMM2: 24 ch

    // buildX constants
    const int bx_kt  = lane >> 2;
    const int bx_pl0 = (2 * lane) & 7;
    const int bx_w0  = (bx_pl0 & 3) * 4;
    const int bx_ph0 = (bx_pl0 >> 2) * 2;
    const int bx_w1  = ((bx_pl0 + 1) & 3) * 4;
    const int bx_ph1 = ((bx_pl0 + 1) >> 2) * 2;

    for (int t = blockIdx.x; t < TILES_SYM; t += GRIDX) {
        // ---- map t -> (i, jb) over the upper-triangle tile set (FIXED) ----
        // prefix boundaries: base(ib) = 128*(8*ib - ib*(ib-1)/2)
        int ib = (t >= 1024) + (t >= 1920) + (t >= 2688) + (t >= 3328)
               + (t >= 3840) + (t >= 4224) + (t >= 4480);
        int base = 128 * (8 * ib - (ib * (ib - 1)) / 2);
        const int local = t - base;
        const int njb   = 8 - ib;
        const int idiv  = local / njb;
        const int i     = ib * 128 + idiv;
        const int jb    = ib + (local - idiv * njb);

        // ---------- buildX: warp-cooperative, 1 row per step ----------
        {
            const float4 fi4 = ((const float4*)(feat + i * FF))[lane];
#pragma unroll
            for (int rr = 0; rr < 8; ++rr) {
                int p = wid * 8 + rr;
                float4 fj4 = ((const float4*)(feat + (jb * 128 + p) * FF))[lane];
                float x0 = fabsf(fi4.x - fj4.x);
                float x1 = fabsf(fi4.y - fj4.y);
                float x2 = fabsf(fi4.z - fj4.z);
                float x3 = fabsf(fi4.w - fj4.w);
                uint32_t wA = pack_bf16x2(x0, x1);
                uint32_t wB = pack_bf16x2(x2, x3);
                int mt = p >> 4, r16 = p & 15;
                int gg = r16 & 7, rowbit = r16 >> 3;
                int bidx = ((mt * 8 + bx_kt) * 33 + gg * 4) * 4;
                Xw[bidx + bx_w0 + bx_ph0 + rowbit] = wA;
                Xw[bidx + bx_w1 + bx_ph1 + rowbit] = wB;
            }
        }
        __syncthreads();

        // ---------- GEMM1: [128 x 192] = X[128 x 128] * W0'^T ----------
        float c1r[2][6][4];
#pragma unroll
        for (int mt = 0; mt < 2; ++mt)
#pragma unroll
            for (int nt = 0; nt < 6; ++nt)
#pragma unroll
                for (int r = 0; r < 4; ++r) c1r[mt][nt][r] = 0.0f;

#pragma unroll
        for (int kt = 0; kt < 8; ++kt) {
            uint4 a[2];
#pragma unroll
            for (int mt = 0; mt < 2; ++mt)
                a[mt] = XF4[((wm * 2 + mt) * 8 + kt) * 33 + lane];
#pragma unroll
            for (int q = 0; q < 3; ++q) {
                uint4 b = W0F4[((wn * 3 + q) * 8 + kt) * 32 + lane];
#pragma unroll
                for (int mt = 0; mt < 2; ++mt) {
                    mma_bf16(c1r[mt][q * 2 + 0], (const uint32_t*)&a[mt], b.x, b.y);
                    mma_bf16(c1r[mt][q * 2 + 1], (const uint32_t*)&a[mt], b.z, b.w);
                }
            }
        }

        // ---------- epilogue1: BN shift + leaky -> H frags (1 STS.128 per frag) ----------
#pragma unroll
        for (int mt = 0; mt < 2; ++mt) {
            int mtg = wm * 2 + mt;
#pragma unroll
            for (int q = 0; q < 3; ++q) {
                int nt0 = 2 * q, nt1 = 2 * q + 1;
                int colA = wn * 48 + nt0 * 8 + 2 * t4;
                int colB = wn * 48 + nt1 * 8 + 2 * t4;
                float sA0 = bn0S[colA], sA1 = bn0S[colA + 1];
                float sB0 = bn0S[colB], sB1 = bn0S[colB + 1];
                uint4 val;
                val.x = pack_bf16x2(leaky(c1r[mt][nt0][0] + sA0),
                                    leaky(c1r[mt][nt0][1] + sA1));
                val.y = pack_bf16x2(leaky(c1r[mt][nt0][2] + sA0),
                                    leaky(c1r[mt][nt0][3] + sA1));
                val.z = pack_bf16x2(leaky(c1r[mt][nt1][0] + sB0),
                                    leaky(c1r[mt][nt1][1] + sB1));
                val.w = pack_bf16x2(leaky(c1r[mt][nt1][2] + sB0),
                                    leaky(c1r[mt][nt1][3] + sB1));
                HF4[(mtg * 12 + wn * 3 + q) * 32 + lane] = val;
            }
        }
        __syncthreads();

        // ---------- GEMM2: [128 x 96] = H[128 x 192] * W1'^T ----------
        float c2r[2][3][4];
#pragma unroll
        for (int mt = 0; mt < 2; ++mt)
#pragma unroll
            for (int nt = 0; nt < 3; ++nt)
#pragma unroll
                for (int r = 0; r < 4; ++r) c2r[mt][nt][r] = 0.0f;

#pragma unroll
        for (int kt = 0; kt < 12; ++kt) {
            uint4 a[2];
#pragma unroll
            for (int mt = 0; mt < 2; ++mt)
                a[mt] = HF4[((wm * 2 + mt) * 12 + kt) * 32 + lane];
#pragma unroll
            for (int nt = 0; nt < 3; ++nt) {
                uint2 b = W1F[((wn * 3 + nt) * 12 + kt) * 32 + lane];
#pragma unroll
                for (int mt = 0; mt < 2; ++mt)
                    mma_bf16(c2r[mt][nt], (const uint32_t*)&a[mt], b.x, b.y);
            }
        }

        // ---------- epilogue2: BN shift + leaky + Wout dot + reduce ----------
#pragma unroll
        for (int mt = 0; mt < 2; ++mt) {
#pragma unroll
            for (int half = 0; half < 2; ++half) {
                float acc = 0.0f;
#pragma unroll
                for (int nt = 0; nt < 3; ++nt) {
                    int col0 = wn * 24 + nt * 8 + 2 * t4;
                    float h0 = leaky(c2r[mt][nt][half * 2 + 0] + bn1S[col0]);
                    float h1 = leaky(c2r[mt][nt][half * 2 + 1] + bn1S[col0 + 1]);
                    acc += woutS[col0] * h0 + woutS[col0 + 1] * h1;
                }
                acc += __shfl_xor_sync(0xffffffffu, acc, 1);
                acc += __shfl_xor_sync(0xffffffffu, acc, 2);
                if (t4 == 0) {
                    int row = (wm * 2 + mt) * 16 + half * 8 + g;
                    redS[wn * 128 + row] = acc;
                }
            }
        }
        __syncthreads();
        if (tid < 128) {
            float logit = redS[tid] + redS[128 + tid] + redS[256 + tid]
                        + redS[384 + tid] + boutv;
            float s = 1.0f / (1.0f + __expf(-logit));
            int jcol = jb * 128 + tid;
            sim_out[i * NN + jcol] = s;
            sim_out[jcol * NN + i] = s;   // symmetric mirror
        }
        __syncthreads();   // protect redS + X frags before next tile
    }
}

// ---- pass 2: partial column sums of sim over 128-row slabs ----
__device__ float g_colpart[8][NN];

__global__ void colsum_kernel(const float* __restrict__ sim) {
    int j = blockIdx.x * 256 + threadIdx.x;
    int slab = blockIdx.y;
    float s = 0.0f;
    int ibase = slab * 128;
#pragma unroll 8
    for (int i = 0; i < 128; ++i) s += sim[(ibase + i) * NN + j];
    g_colpart[slab][j] = s;
}

// ---- pass 3: edge = (sim + eye + 1e-6) / colsum_over_i ----
__global__ void edge_kernel(const float* __restrict__ sim, float* __restrict__ edge) {
    int idx = blockIdx.x * 256 + threadIdx.x;
    int i = idx >> 10;
    int j = idx & (NN - 1);
    float denom = 1.0f + NN * 1e-6f;
#pragma unroll
    for (int r = 0; r < 8; ++r) denom += g_colpart[r][j];
    float v = sim[idx] + ((i == j) ? 1.0f : 0.0f) + 1e-6f;
    edge[idx] = v / denom;
}

extern "C" void kernel_launch(void* const* d_in, const int* in_sizes, int n_in,
                              void* d_out, int out_size) {
    const float* feat = (const float*)d_in[0];
    const float* W0   = (const float*)d_in[1];
    const float* g0   = (const float*)d_in[2];
    const float* b0   = (const float*)d_in[3];
    const float* m0   = (const float*)d_in[4];
    const float* v0   = (const float*)d_in[5];
    const float* W1   = (const float*)d_in[6];
    const float* g1   = (const float*)d_in[7];
    const float* b1   = (const float*)d_in[8];
    const float* m1   = (const float*)d_in[9];
    const float* v1   = (const float*)d_in[10];
    const float* Wout = (const float*)d_in[11];
    const float* bout = (const float*)d_in[12];

    float* out  = (float*)d_out;
    float* edge = out;              // edge_feat [1,N,N] first
    float* sim  = out + NN * NN;    // sim_val [N,N] second

    cudaFuncSetAttribute(edgenet_bf16_kernel,
                         cudaFuncAttributeMaxDynamicSharedMemorySize, SMEM_BYTES);

    edgenet_bf16_kernel<<<GRIDX, THREADS, SMEM_BYTES>>>(
        feat, W0, g0, b0, m0, v0, W1, g1, b1, m1, v1, Wout, bout, sim);

    colsum_kernel<<<dim3(4, 8), 256>>>(sim);
    edge_kernel<<<(NN * NN) / 256, 256>>>(sim, edge);
}

// round 10
// speedup vs baseline: 11.0303x; 1.4742x over previous
#include <cuda_runtime.h>
#include <math.h>
#include <cstdint>

#define NN 1024
#define FF 128
#define H0C 192
#define H1C 96
#define THREADS 768
#define GRIDX 148
#define TILES_SYM 4608       // sum over ib of 128*(8-ib)

// ---------------- SMEM layout (bytes) ----------------
#define SM_W0F   0           // 12 qg * 8 kt * 32 * 16B = 49152
#define SM_W1F   49152       // 6 qg * 12 kt * 32 * 16B = 36864
#define SM_XF    86016       // 8 mt * 8 kt frags, 33-uint4 stride = 33792
#define SM_HF    119808      // 8 mt * 12 kt * 32 * 16B = 49152
#define SM_BN0   168960      // 192 floats
#define SM_BN1   169728      // 96 floats
#define SM_WOUT  170112      // 96 floats
#define SM_RED   170496      // 6*128 floats = 3072
#define SM_BOUT  173568
#define SMEM_BYTES 173584

__device__ __forceinline__ uint32_t pack_bf16x2(float lo, float hi) {
    uint32_t r;
    asm("cvt.rn.bf16x2.f32 %0, %1, %2;" : "=r"(r) : "f"(hi), "f"(lo));
    return r;
}
__device__ __forceinline__ float leaky(float x) {
    return fmaxf(x, 0.0f) + 0.01f * fminf(x, 0.0f);
}
__device__ __forceinline__ void mma_bf16(float* d, const uint32_t* a,
                                         uint32_t b0, uint32_t b1) {
    asm volatile(
        "mma.sync.aligned.m16n8k16.row.col.f32.bf16.bf16.f32 "
        "{%0,%1,%2,%3}, {%4,%5,%6,%7}, {%8,%9}, {%0,%1,%2,%3};"
        : "+f"(d[0]), "+f"(d[1]), "+f"(d[2]), "+f"(d[3])
        : "r"(a[0]), "r"(a[1]), "r"(a[2]), "r"(a[3]), "r"(b0), "r"(b1));
}

__global__ void __launch_bounds__(THREADS, 1) edgenet_bf16_kernel(
    const float* __restrict__ feat,
    const float* __restrict__ W0, const float* __restrict__ g0,
    const float* __restrict__ b0, const float* __restrict__ m0,
    const float* __restrict__ v0,
    const float* __restrict__ W1, const float* __restrict__ g1,
    const float* __restrict__ b1, const float* __restrict__ m1,
    const float* __restrict__ v1,
    const float* __restrict__ Wout, const float* __restrict__ bout,
    float* __restrict__ sim_out)
{
    extern __shared__ char smem[];
    uint4*    W0F4 = (uint4*)(smem + SM_W0F);
    uint4*    W1F4 = (uint4*)(smem + SM_W1F);
    uint4*    XF4  = (uint4*)(smem + SM_XF);
    uint32_t* Xw   = (uint32_t*)(smem + SM_XF);
    uint4*    HF4  = (uint4*)(smem + SM_HF);
    float*    bn0S = (float*)(smem + SM_BN0);
    float*    bn1S = (float*)(smem + SM_BN1);
    float*    woutS= (float*)(smem + SM_WOUT);
    float*    redS = (float*)(smem + SM_RED);
    float*    boutS= (float*)(smem + SM_BOUT);

    const int tid  = threadIdx.x;
    const int wid  = tid >> 5;
    const int lane = tid & 31;
    const int g    = lane >> 2;
    const int t4   = lane & 3;

    // ---- stage weights ONCE as bf16 B-fragments (BN scale folded) ----
    // W0 uint4: qg pairs channel-blocks (2qg, 2qg+1): c0 = 16qg + g, c1 = c0+8
    for (int idx = tid; idx < 12 * 8 * 32; idx += THREADS) {
        int qg = idx >> 8, kt = (idx >> 5) & 7, ln = idx & 31;
        int c0 = qg * 16 + (ln >> 2);
        int c1 = c0 + 8;
        int f  = kt * 16 + (ln & 3) * 2;
        float s0 = g0[c0] * rsqrtf(v0[c0] + 1e-5f);
        float s1 = g0[c1] * rsqrtf(v0[c1] + 1e-5f);
        uint4 b;
        b.x = pack_bf16x2(W0[c0 * FF + f] * s0,     W0[c0 * FF + f + 1] * s0);
        b.y = pack_bf16x2(W0[c0 * FF + f + 8] * s0, W0[c0 * FF + f + 9] * s0);
        b.z = pack_bf16x2(W0[c1 * FF + f] * s1,     W0[c1 * FF + f + 1] * s1);
        b.w = pack_bf16x2(W0[c1 * FF + f + 8] * s1, W0[c1 * FF + f + 9] * s1);
        W0F4[idx] = b;
    }
    // W1 uint4: qg (0..5) pairs channel-blocks: d0 = 16qg + g, d1 = d0+8
    for (int idx = tid; idx < 6 * 12 * 32; idx += THREADS) {
        int qg = idx / 384, kt = (idx / 32) % 12, ln = idx & 31;
        int d0 = qg * 16 + (ln >> 2);
        int d1 = d0 + 8;
        int k  = kt * 16 + (ln & 3) * 2;
        float s0 = g1[d0] * rsqrtf(v1[d0] + 1e-5f);
        float s1 = g1[d1] * rsqrtf(v1[d1] + 1e-5f);
        uint4 b;
        b.x = pack_bf16x2(W1[d0 * H0C + k] * s0,     W1[d0 * H0C + k + 1] * s0);
        b.y = pack_bf16x2(W1[d0 * H0C + k + 8] * s0, W1[d0 * H0C + k + 9] * s0);
        b.z = pack_bf16x2(W1[d1 * H0C + k] * s1,     W1[d1 * H0C + k + 1] * s1);
        b.w = pack_bf16x2(W1[d1 * H0C + k + 8] * s1, W1[d1 * H0C + k + 9] * s1);
        W1F4[idx] = b;
    }
    for (int c = tid; c < H0C; c += THREADS) {
        float s = g0[c] * rsqrtf(v0[c] + 1e-5f);
        bn0S[c] = b0[c] - m0[c] * s;
    }
    for (int d = tid; d < H1C; d += THREADS) {
        float s = g1[d] * rsqrtf(v1[d] + 1e-5f);
        bn1S[d] = b1[d] - m1[d] * s;
        woutS[d] = Wout[d];
    }
    if (tid == 0) boutS[0] = bout[0];
    __syncthreads();
    const float boutv = boutS[0];

    // warp roles: 4 m-groups x 6 n-groups
    const int wm = wid & 3;     // rows wm*32 .. +31  (2 mt of 16)
    const int wn = wid >> 2;    // GEMM1: 32 ch (2 qg), GEMM2: 16 ch (1 qg)

    // buildX constants
    const int bx_kt  = lane >> 2;
    const int bx_pl0 = (2 * lane) & 7;
    const int bx_w0  = (bx_pl0 & 3) * 4;
    const int bx_ph0 = (bx_pl0 >> 2) * 2;
    const int bx_w1  = ((bx_pl0 + 1) & 3) * 4;
    const int bx_ph1 = ((bx_pl0 + 1) >> 2) * 2;

    for (int t = blockIdx.x; t < TILES_SYM; t += GRIDX) {
        // ---- map t -> (i, jb) over the upper-triangle tile set ----
        int ib = (t >= 1024) + (t >= 1920) + (t >= 2688) + (t >= 3328)
               + (t >= 3840) + (t >= 4224) + (t >= 4480);
        int base = 128 * (8 * ib - (ib * (ib - 1)) / 2);
        const int local = t - base;
        const int njb   = 8 - ib;
        const int idiv  = local / njb;
        const int i     = ib * 128 + idiv;
        const int jb    = ib + (local - idiv * njb);

        // ---------- buildX: warp-cooperative, rows p = wid + 24*rr ----------
        {
            const float4 fi4 = ((const float4*)(feat + i * FF))[lane];
#pragma unroll
            for (int rr = 0; rr < 6; ++rr) {
                int p = wid + 24 * rr;
                if (p < 128) {
                    float4 fj4 = ((const float4*)(feat + (jb * 128 + p) * FF))[lane];
                    float x0 = fabsf(fi4.x - fj4.x);
                    float x1 = fabsf(fi4.y - fj4.y);
                    float x2 = fabsf(fi4.z - fj4.z);
                    float x3 = fabsf(fi4.w - fj4.w);
                    uint32_t wA = pack_bf16x2(x0, x1);
                    uint32_t wB = pack_bf16x2(x2, x3);
                    int mt = p >> 4, r16 = p & 15;
                    int gg = r16 & 7, rowbit = r16 >> 3;
                    int bidx = ((mt * 8 + bx_kt) * 33 + gg * 4) * 4;
                    Xw[bidx + bx_w0 + bx_ph0 + rowbit] = wA;
                    Xw[bidx + bx_w1 + bx_ph1 + rowbit] = wB;
                }
            }
        }
        __syncthreads();

        // ---------- GEMM1: [128 x 192] = X[128 x 128] * W0'^T ----------
        float c1r[2][4][4];
#pragma unroll
        for (int mt = 0; mt < 2; ++mt)
#pragma unroll
            for (int nt = 0; nt < 4; ++nt)
#pragma unroll
                for (int r = 0; r < 4; ++r) c1r[mt][nt][r] = 0.0f;

#pragma unroll
        for (int kt = 0; kt < 8; ++kt) {
            uint4 a[2];
#pragma unroll
            for (int mt = 0; mt < 2; ++mt)
                a[mt] = XF4[((wm * 2 + mt) * 8 + kt) * 33 + lane];
#pragma unroll
            for (int q = 0; q < 2; ++q) {
                uint4 b = W0F4[((wn * 2 + q) * 8 + kt) * 32 + lane];
#pragma unroll
                for (int mt = 0; mt < 2; ++mt) {
                    mma_bf16(c1r[mt][q * 2 + 0], (const uint32_t*)&a[mt], b.x, b.y);
                    mma_bf16(c1r[mt][q * 2 + 1], (const uint32_t*)&a[mt], b.z, b.w);
                }
            }
        }

        // ---------- epilogue1: BN shift + leaky -> H frags (STS.128) ----------
#pragma unroll
        for (int mt = 0; mt < 2; ++mt) {
            int mtg = wm * 2 + mt;
#pragma unroll
            for (int q = 0; q < 2; ++q) {
                int colA = wn * 32 + q * 16 + 2 * t4;
                int colB = colA + 8;
                float sA0 = bn0S[colA], sA1 = bn0S[colA + 1];
                float sB0 = bn0S[colB], sB1 = bn0S[colB + 1];
                uint4 val;
                val.x = pack_bf16x2(leaky(c1r[mt][q * 2][0] + sA0),
                                    leaky(c1r[mt][q * 2][1] + sA1));
                val.y = pack_bf16x2(leaky(c1r[mt][q * 2][2] + sA0),
                                    leaky(c1r[mt][q * 2][3] + sA1));
                val.z = pack_bf16x2(leaky(c1r[mt][q * 2 + 1][0] + sB0),
                                    leaky(c1r[mt][q * 2 + 1][1] + sB1));
                val.w = pack_bf16x2(leaky(c1r[mt][q * 2 + 1][2] + sB0),
                                    leaky(c1r[mt][q * 2 + 1][3] + sB1));
                HF4[(mtg * 12 + wn * 2 + q) * 32 + lane] = val;
            }
        }
        __syncthreads();

        // ---------- GEMM2: [128 x 96] = H[128 x 192] * W1'^T ----------
        float c2r[2][2][4];
#pragma unroll
        for (int mt = 0; mt < 2; ++mt)
#pragma unroll
            for (int nt = 0; nt < 2; ++nt)
#pragma unroll
                for (int r = 0; r < 4; ++r) c2r[mt][nt][r] = 0.0f;

#pragma unroll
        for (int kt = 0; kt < 12; ++kt) {
            uint4 a[2];
#pragma unroll
            for (int mt = 0; mt < 2; ++mt)
                a[mt] = HF4[((wm * 2 + mt) * 12 + kt) * 32 + lane];
            uint4 b = W1F4[(wn * 12 + kt) * 32 + lane];
#pragma unroll
            for (int mt = 0; mt < 2; ++mt) {
                mma_bf16(c2r[mt][0], (const uint32_t*)&a[mt], b.x, b.y);
                mma_bf16(c2r[mt][1], (const uint32_t*)&a[mt], b.z, b.w);
            }
        }

        // ---------- epilogue2: BN shift + leaky + Wout dot + reduce ----------
#pragma unroll
        for (int mt = 0; mt < 2; ++mt) {
#pragma unroll
            for (int half = 0; half < 2; ++half) {
                float acc = 0.0f;
#pragma unroll
                for (int nt = 0; nt < 2; ++nt) {
                    int col0 = wn * 16 + nt * 8 + 2 * t4;
                    float h0 = leaky(c2r[mt][nt][half * 2 + 0] + bn1S[col0]);
                    float h1 = leaky(c2r[mt][nt][half * 2 + 1] + bn1S[col0 + 1]);
                    acc += woutS[col0] * h0 + woutS[col0 + 1] * h1;
                }
                acc += __shfl_xor_sync(0xffffffffu, acc, 1);
                acc += __shfl_xor_sync(0xffffffffu, acc, 2);
                if (t4 == 0) {
                    int row = (wm * 2 + mt) * 16 + half * 8 + g;
                    redS[wn * 128 + row] = acc;
                }
            }
        }
        __syncthreads();
        if (tid < 128) {
            float logit = redS[tid] + redS[128 + tid] + redS[256 + tid]
                        + redS[384 + tid] + redS[512 + tid] + redS[640 + tid]
                        + boutv;
            float s = 1.0f / (1.0f + __expf(-logit));
            int jcol = jb * 128 + tid;
            sim_out[i * NN + jcol] = s;
            sim_out[jcol * NN + i] = s;   // symmetric mirror
        }
        // no trailing sync needed: >=2 syncs separate every cross-tile hazard
    }
}

// ---- pass 2: partial column sums of sim over 128-row slabs ----
__device__ float g_colpart[8][NN];

__global__ void colsum_kernel(const float* __restrict__ sim) {
    int j = blockIdx.x * 256 + threadIdx.x;
    int slab = blockIdx.y;
    float s = 0.0f;
    int ibase = slab * 128;
#pragma unroll 8
    for (int i = 0; i < 128; ++i) s += sim[(ibase + i) * NN + j];
    g_colpart[slab][j] = s;
}

// ---- pass 3: edge = (sim + eye + 1e-6) / colsum_over_i ----
__global__ void edge_kernel(const float* __restrict__ sim, float* __restrict__ edge) {
    int idx = blockIdx.x * 256 + threadIdx.x;
    int i = idx >> 10;
    int j = idx & (NN - 1);
    float denom = 1.0f + NN * 1e-6f;
#pragma unroll
    for (int r = 0; r < 8; ++r) denom += g_colpart[r][j];
    float v = sim[idx] + ((i == j) ? 1.0f : 0.0f) + 1e-6f;
    edge[idx] = v / denom;
}

extern "C" void kernel_launch(void* const* d_in, const int* in_sizes, int n_in,
                              void* d_out, int out_size) {
    const float* feat = (const float*)d_in[0];
    const float* W0   = (const float*)d_in[1];
    const float* g0   = (const float*)d_in[2];
    const float* b0   = (const float*)d_in[3];
    const float* m0   = (const float*)d_in[4];
    const float* v0   = (const float*)d_in[5];
    const float* W1   = (const float*)d_in[6];
    const float* g1   = (const float*)d_in[7];
    const float* b1   = (const float*)d_in[8];
    const float* m1   = (const float*)d_in[9];
    const float* v1   = (const float*)d_in[10];
    const float* Wout = (const float*)d_in[11];
    const float* bout = (const float*)d_in[12];

    float* out  = (float*)d_out;
    float* edge = out;              // edge_feat [1,N,N] first
    float* sim  = out + NN * NN;    // sim_val [N,N] second

    cudaFuncSetAttribute(edgenet_bf16_kernel,
                         cudaFuncAttributeMaxDynamicSharedMemorySize, SMEM_BYTES);

    edgenet_bf16_kernel<<<GRIDX, THREADS, SMEM_BYTES>>>(
        feat, W0, g0, b0, m0, v0, W1, g1, b1, m1, v1, Wout, bout, sim);

    colsum_kernel<<<dim3(4, 8), 256>>>(sim);
    edge_kernel<<<(NN * NN) / 256, 256>>>(sim, edge);
}

// round 11
// speedup vs baseline: 11.7437x; 1.0647x over previous
#include <cuda_runtime.h>
#include <math.h>
#include <cstdint>

#define NN 1024
#define FF 128
#define H0C 192
#define H1C 96
#define THREADS 768
#define GRIDX 148
#define TILES_SYM 4608       // sum over ib of 128*(8-ib)

// ---------------- SMEM layout (bytes) ----------------
#define SM_W0F   0           // 12 qg * 8 kt * 32 * 16B = 49152
#define SM_W1F   49152       // 6 qg * 12 kt * 32 * 16B = 36864
#define SM_XF    86016       // 8 mt * 8 kt frags, 33-uint4 stride = 33792
#define SM_HF    119808      // 8 mt * 12 kt * 32 * 16B = 49152
#define SM_BN0   168960      // 192 floats
#define SM_BN1   169728      // 96 floats
#define SM_WOUT  170112      // 96 floats
#define SM_RED   170496      // 6*128 floats = 3072
#define SM_BOUT  173568
#define SMEM_BYTES 173584

__device__ __forceinline__ uint32_t pack_bf16x2(float lo, float hi) {
    uint32_t r;
    asm("cvt.rn.bf16x2.f32 %0, %1, %2;" : "=r"(r) : "f"(hi), "f"(lo));
    return r;
}
__device__ __forceinline__ float leaky(float x) {
    return fmaxf(x, 0.0f) + 0.01f * fminf(x, 0.0f);
}
__device__ __forceinline__ void mma_bf16(float* d, const uint32_t* a,
                                         uint32_t b0, uint32_t b1) {
    asm volatile(
        "mma.sync.aligned.m16n8k16.row.col.f32.bf16.bf16.f32 "
        "{%0,%1,%2,%3}, {%4,%5,%6,%7}, {%8,%9}, {%0,%1,%2,%3};"
        : "+f"(d[0]), "+f"(d[1]), "+f"(d[2]), "+f"(d[3])
        : "r"(a[0]), "r"(a[1]), "r"(a[2]), "r"(a[3]), "r"(b0), "r"(b1));
}
// group-scoped named barrier: 6 warps (192 threads) of wm-group
__device__ __forceinline__ void group_bar(int wm) {
    asm volatile("bar.sync %0, %1;" :: "r"(1 + wm), "r"(192) : "memory");
}

__global__ void __launch_bounds__(THREADS, 1) edgenet_bf16_kernel(
    const float* __restrict__ feat,
    const float* __restrict__ W0, const float* __restrict__ g0,
    const float* __restrict__ b0, const float* __restrict__ m0,
    const float* __restrict__ v0,
    const float* __restrict__ W1, const float* __restrict__ g1,
    const float* __restrict__ b1, const float* __restrict__ m1,
    const float* __restrict__ v1,
    const float* __restrict__ Wout, const float* __restrict__ bout,
    float* __restrict__ sim_out)
{
    extern __shared__ char smem[];
    uint4*    W0F4 = (uint4*)(smem + SM_W0F);
    uint4*    W1F4 = (uint4*)(smem + SM_W1F);
    uint4*    XF4  = (uint4*)(smem + SM_XF);
    uint32_t* Xw   = (uint32_t*)(smem + SM_XF);
    uint4*    HF4  = (uint4*)(smem + SM_HF);
    float*    bn0S = (float*)(smem + SM_BN0);
    float*    bn1S = (float*)(smem + SM_BN1);
    float*    woutS= (float*)(smem + SM_WOUT);
    float*    redS = (float*)(smem + SM_RED);
    float*    boutS= (float*)(smem + SM_BOUT);

    const int tid  = threadIdx.x;
    const int wid  = tid >> 5;
    const int lane = tid & 31;
    const int g    = lane >> 2;
    const int t4   = lane & 3;

    // ---- stage weights ONCE as bf16 B-fragments (BN scale folded) ----
    for (int idx = tid; idx < 12 * 8 * 32; idx += THREADS) {
        int qg = idx >> 8, kt = (idx >> 5) & 7, ln = idx & 31;
        int c0 = qg * 16 + (ln >> 2);
        int c1 = c0 + 8;
        int f  = kt * 16 + (ln & 3) * 2;
        float s0 = g0[c0] * rsqrtf(v0[c0] + 1e-5f);
        float s1 = g0[c1] * rsqrtf(v0[c1] + 1e-5f);
        uint4 b;
        b.x = pack_bf16x2(W0[c0 * FF + f] * s0,     W0[c0 * FF + f + 1] * s0);
        b.y = pack_bf16x2(W0[c0 * FF + f + 8] * s0, W0[c0 * FF + f + 9] * s0);
        b.z = pack_bf16x2(W0[c1 * FF + f] * s1,     W0[c1 * FF + f + 1] * s1);
        b.w = pack_bf16x2(W0[c1 * FF + f + 8] * s1, W0[c1 * FF + f + 9] * s1);
        W0F4[idx] = b;
    }
    for (int idx = tid; idx < 6 * 12 * 32; idx += THREADS) {
        int qg = idx / 384, kt = (idx / 32) % 12, ln = idx & 31;
        int d0 = qg * 16 + (ln >> 2);
        int d1 = d0 + 8;
        int k  = kt * 16 + (ln & 3) * 2;
        float s0 = g1[d0] * rsqrtf(v1[d0] + 1e-5f);
        float s1 = g1[d1] * rsqrtf(v1[d1] + 1e-5f);
        uint4 b;
        b.x = pack_bf16x2(W1[d0 * H0C + k] * s0,     W1[d0 * H0C + k + 1] * s0);
        b.y = pack_bf16x2(W1[d0 * H0C + k + 8] * s0, W1[d0 * H0C + k + 9] * s0);
        b.z = pack_bf16x2(W1[d1 * H0C + k] * s1,     W1[d1 * H0C + k + 1] * s1);
        b.w = pack_bf16x2(W1[d1 * H0C + k + 8] * s1, W1[d1 * H0C + k + 9] * s1);
        W1F4[idx] = b;
    }
    for (int c = tid; c < H0C; c += THREADS) {
        float s = g0[c] * rsqrtf(v0[c] + 1e-5f);
        bn0S[c] = b0[c] - m0[c] * s;
    }
    for (int d = tid; d < H1C; d += THREADS) {
        float s = g1[d] * rsqrtf(v1[d] + 1e-5f);
        bn1S[d] = b1[d] - m1[d] * s;
        woutS[d] = Wout[d];
    }
    if (tid == 0) boutS[0] = bout[0];
    __syncthreads();
    const float boutv = boutS[0];

    // warp roles: 4 m-groups (wm) x 6 n-groups (wn)
    const int wm = wid & 3;
    const int wn = wid >> 2;

    // buildX constants
    const int bx_kt  = lane >> 2;
    const int bx_pl0 = (2 * lane) & 7;
    const int bx_w0  = (bx_pl0 & 3) * 4;
    const int bx_ph0 = (bx_pl0 >> 2) * 2;
    const int bx_w1  = ((bx_pl0 + 1) & 3) * 4;
    const int bx_ph1 = ((bx_pl0 + 1) >> 2) * 2;

    for (int t = blockIdx.x; t < TILES_SYM; t += GRIDX) {
        // ---- map t -> (i, jb) over the upper-triangle tile set ----
        int ib = (t >= 1024) + (t >= 1920) + (t >= 2688) + (t >= 3328)
               + (t >= 3840) + (t >= 4224) + (t >= 4480);
        int base = 128 * (8 * ib - (ib * (ib - 1)) / 2);
        const int local = t - base;
        const int njb   = 8 - ib;
        const int idiv  = local / njb;
        const int i     = ib * 128 + idiv;
        const int jb    = ib + (local - idiv * njb);

        // ---------- buildX: GROUP-LOCAL rows p = wm*32 + wn + 6*rr ----------
        {
            const float4 fi4 = ((const float4*)(feat + i * FF))[lane];
#pragma unroll
            for (int rr = 0; rr < 6; ++rr) {
                int pl = wn + 6 * rr;
                if (pl < 32) {
                    int p = wm * 32 + pl;
                    float4 fj4 = ((const float4*)(feat + (jb * 128 + p) * FF))[lane];
                    float x0 = fabsf(fi4.x - fj4.x);
                    float x1 = fabsf(fi4.y - fj4.y);
                    float x2 = fabsf(fi4.z - fj4.z);
                    float x3 = fabsf(fi4.w - fj4.w);
                    uint32_t wA = pack_bf16x2(x0, x1);
                    uint32_t wB = pack_bf16x2(x2, x3);
                    int mt = p >> 4, r16 = p & 15;
                    int gg = r16 & 7, rowbit = r16 >> 3;
                    int bidx = ((mt * 8 + bx_kt) * 33 + gg * 4) * 4;
                    Xw[bidx + bx_w0 + bx_ph0 + rowbit] = wA;
                    Xw[bidx + bx_w1 + bx_ph1 + rowbit] = wB;
                }
            }
        }
        group_bar(wm);   // XF[wm rows] built by this group only

        // ---------- GEMM1: [32 rows x 192] slice of X * W0'^T ----------
        float c1r[2][4][4];
#pragma unroll
        for (int mt = 0; mt < 2; ++mt)
#pragma unroll
            for (int nt = 0; nt < 4; ++nt)
#pragma unroll
                for (int r = 0; r < 4; ++r) c1r[mt][nt][r] = 0.0f;

#pragma unroll
        for (int kt = 0; kt < 8; ++kt) {
            uint4 a[2];
#pragma unroll
            for (int mt = 0; mt < 2; ++mt)
                a[mt] = XF4[((wm * 2 + mt) * 8 + kt) * 33 + lane];
#pragma unroll
            for (int q = 0; q < 2; ++q) {
                uint4 b = W0F4[((wn * 2 + q) * 8 + kt) * 32 + lane];
#pragma unroll
                for (int mt = 0; mt < 2; ++mt) {
                    mma_bf16(c1r[mt][q * 2 + 0], (const uint32_t*)&a[mt], b.x, b.y);
                    mma_bf16(c1r[mt][q * 2 + 1], (const uint32_t*)&a[mt], b.z, b.w);
                }
            }
        }

        // ---------- epilogue1: BN shift + leaky -> HF[wm rows] ----------
#pragma unroll
        for (int mt = 0; mt < 2; ++mt) {
            int mtg = wm * 2 + mt;
#pragma unroll
            for (int q = 0; q < 2; ++q) {
                int colA = wn * 32 + q * 16 + 2 * t4;
                int colB = colA + 8;
                float sA0 = bn0S[colA], sA1 = bn0S[colA + 1];
                float sB0 = bn0S[colB], sB1 = bn0S[colB + 1];
                uint4 val;
                val.x = pack_bf16x2(leaky(c1r[mt][q * 2][0] + sA0),
                                    leaky(c1r[mt][q * 2][1] + sA1));
                val.y = pack_bf16x2(leaky(c1r[mt][q * 2][2] + sA0),
                                    leaky(c1r[mt][q * 2][3] + sA1));
                val.z = pack_bf16x2(leaky(c1r[mt][q * 2 + 1][0] + sB0),
                                    leaky(c1r[mt][q * 2 + 1][1] + sB1));
                val.w = pack_bf16x2(leaky(c1r[mt][q * 2 + 1][2] + sB0),
                                    leaky(c1r[mt][q * 2 + 1][3] + sB1));
                HF4[(mtg * 12 + wn * 2 + q) * 32 + lane] = val;
            }
        }
        group_bar(wm);   // HF[wm rows] complete (written by this group only)

        // ---------- GEMM2: [32 rows x 96] = H[wm rows] * W1'^T ----------
        float c2r[2][2][4];
#pragma unroll
        for (int mt = 0; mt < 2; ++mt)
#pragma unroll
            for (int nt = 0; nt < 2; ++nt)
#pragma unroll
                for (int r = 0; r < 4; ++r) c2r[mt][nt][r] = 0.0f;

#pragma unroll
        for (int kt = 0; kt < 12; ++kt) {
            uint4 a[2];
#pragma unroll
            for (int mt = 0; mt < 2; ++mt)
                a[mt] = HF4[((wm * 2 + mt) * 12 + kt) * 32 + lane];
            uint4 b = W1F4[(wn * 12 + kt) * 32 + lane];
#pragma unroll
            for (int mt = 0; mt < 2; ++mt) {
                mma_bf16(c2r[mt][0], (const uint32_t*)&a[mt], b.x, b.y);
                mma_bf16(c2r[mt][1], (const uint32_t*)&a[mt], b.z, b.w);
            }
        }

        // ---------- epilogue2: BN shift + leaky + Wout dot + reduce ----------
#pragma unroll
        for (int mt = 0; mt < 2; ++mt) {
#pragma unroll
            for (int half = 0; half < 2; ++half) {
                float acc = 0.0f;
#pragma unroll
                for (int nt = 0; nt < 2; ++nt) {
                    int col0 = wn * 16 + nt * 8 + 2 * t4;
                    float h0 = leaky(c2r[mt][nt][half * 2 + 0] + bn1S[col0]);
                    float h1 = leaky(c2r[mt][nt][half * 2 + 1] + bn1S[col0 + 1]);
                    acc += woutS[col0] * h0 + woutS[col0 + 1] * h1;
                }
                acc += __shfl_xor_sync(0xffffffffu, acc, 1);
                acc += __shfl_xor_sync(0xffffffffu, acc, 2);
                if (t4 == 0) {
                    int row = (wm * 2 + mt) * 16 + half * 8 + g;
                    redS[wn * 128 + row] = acc;   // row in [wm*32, wm*32+32)
                }
            }
        }
        group_bar(wm);   // redS rows of this wm written only by this group

        // final logit/store: warp `wm` of wn==0 handles rows wm*32..+31
        if (wn == 0) {
            int row = wm * 32 + lane;
            float logit = redS[row] + redS[128 + row] + redS[256 + row]
                        + redS[384 + row] + redS[512 + row] + redS[640 + row]
                        + boutv;
            float s = 1.0f / (1.0f + __expf(-logit));
            int jcol = jb * 128 + row;
            sim_out[i * NN + jcol] = s;
            sim_out[jcol * NN + i] = s;   // symmetric mirror
        }
        // next tile's redS writes by group wm are ordered after this read via
        // this group's next two group_bars (reader warp participates in both)
    }
}

// ---- pass 2: partial column sums of sim over 128-row slabs (float4) ----
__device__ float g_colpart[8][NN];

__global__ void colsum_kernel(const float* __restrict__ sim) {
    int j4 = (blockIdx.x * 256 + threadIdx.x);   // gridDim.x = 1
    int slab = blockIdx.y;
    if (j4 < 256) {
        float4 s = make_float4(0.f, 0.f, 0.f, 0.f);
        int ibase = slab * 128;
#pragma unroll 4
        for (int i = 0; i < 128; ++i) {
            float4 v = ((const float4*)(sim + (ibase + i) * NN))[j4];
            s.x += v.x; s.y += v.y; s.z += v.z; s.w += v.w;
        }
        ((float4*)g_colpart[slab])[j4] = s;
    }
}

// ---- pass 3: edge = (sim + eye + 1e-6) / colsum_over_i (float4) ----
__global__ void edge_kernel(const float* __restrict__ sim, float* __restrict__ edge) {
    int idx4 = blockIdx.x * 256 + threadIdx.x;   // over float4 elements
    int i  = idx4 >> 8;                          // 256 float4 per row
    int j0 = (idx4 & 255) * 4;
    float4 den = make_float4(1.0f + NN * 1e-6f, 1.0f + NN * 1e-6f,
                             1.0f + NN * 1e-6f, 1.0f + NN * 1e-6f);
#pragma unroll
    for (int r = 0; r < 8; ++r) {
        float4 c = ((const float4*)g_colpart[r])[idx4 & 255];
        den.x += c.x; den.y += c.y; den.z += c.z; den.w += c.w;
    }
    float4 v = ((const float4*)sim)[idx4];
    v.x += ((i == j0 + 0) ? 1.0f : 0.0f) + 1e-6f;
    v.y += ((i == j0 + 1) ? 1.0f : 0.0f) + 1e-6f;
    v.z += ((i == j0 + 2) ? 1.0f : 0.0f) + 1e-6f;
    v.w += ((i == j0 + 3) ? 1.0f : 0.0f) + 1e-6f;
    v.x /= den.x; v.y /= den.y; v.z /= den.z; v.w /= den.w;
    ((float4*)edge)[idx4] = v;
}

extern "C" void kernel_launch(void* const* d_in, const int* in_sizes, int n_in,
                              void* d_out, int out_size) {
    const float* feat = (const float*)d_in[0];
    const float* W0   = (const float*)d_in[1];
    const float* g0   = (const float*)d_in[2];
    const float* b0   = (const float*)d_in[3];
    const float* m0   = (const float*)d_in[4];
    const float* v0   = (const float*)d_in[5];
    const float* W1   = (const float*)d_in[6];
    const float* g1   = (const float*)d_in[7];
    const float* b1   = (const float*)d_in[8];
    const float* m1   = (const float*)d_in[9];
    const float* v1   = (const float*)d_in[10];
    const float* Wout = (const float*)d_in[11];
    const float* bout = (const float*)d_in[12];

    float* out  = (float*)d_out;
    float* edge = out;              // edge_feat [1,N,N] first
    float* sim  = out + NN * NN;    // sim_val [N,N] second

    cudaFuncSetAttribute(edgenet_bf16_kernel,
                         cudaFuncAttributeMaxDynamicSharedMemorySize, SMEM_BYTES);

    edgenet_bf16_kernel<<<GRIDX, THREADS, SMEM_BYTES>>>(
        feat, W0, g0, b0, m0, v0, W1, g1, b1, m1, v1, Wout, bout, sim);

    colsum_kernel<<<dim3(1, 8), 256>>>(sim);
    edge_kernel<<<(NN * NN / 4) / 256, 256>>>(sim, edge);
}